// round 7
// baseline (speedup 1.0000x reference)
#include <cuda_runtime.h>
#include <cstdint>

#define BB 8
#define NN 65536
#define CC 512
#define DD 128
#define ITERS 10
#define TILE_P 128
#define CAP 4

#define PSTR 132   // floats per tf32-point row (132 % 32 == 4 -> conflict-free)
#define CSTR 132   // floats per tf32-center row

// smem floats: ptsT 128*132, cenT 64*132, cn 512, cand 128*16 ints
#define SMEM_FLOATS (128*PSTR + 64*CSTR + CC + 128*16)
#define SMEM_BYTES  (SMEM_FLOATS * 4)

__device__ float g_centers[BB*CC*DD];
__device__ float g_ctf[BB*CC*DD];        // tf32-rounded centers (per iter)
__device__ float g_ptf[BB*NN*DD];        // tf32-rounded points (once)
__device__ float g_cnorm[BB*CC];
__device__ float g_t2max[BB];
__device__ float g_t1[BB*NN];
__device__ int   g_assign[BB*NN];
__device__ int   g_list[BB*NN];
__device__ int   g_off[BB*CC];
__device__ int   g_cnt[BB*CC];

__device__ __forceinline__ float tf32r(float x) {
    uint32_t u;
    asm("cvt.rna.tf32.f32 %0, %1;" : "=r"(u) : "f"(x));
    return __uint_as_float(u);
}
__device__ __forceinline__ void mma_tf32_k4(float& d0, float& d1, float& d2,
                                            float& d3, uint32_t a0, uint32_t a1,
                                            uint32_t b0) {
    asm volatile(
        "mma.sync.aligned.m16n8k4.row.col.f32.tf32.tf32.f32 "
        "{%0,%1,%2,%3}, {%4,%5}, {%6}, {%0,%1,%2,%3};"
        : "+f"(d0), "+f"(d1), "+f"(d2), "+f"(d3)
        : "r"(a0), "r"(a1), "r"(b0));
}

// ---------------- exact-arithmetic building blocks (DO NOT REORDER) --------
// LLVM-style vectorized sum of v[k]^2: VF=4, IC=2, fma, lanewise, faddp.
__device__ __forceinline__ float norm128_llvm(const float* __restrict__ v) {
    float A0=0.f,A1=0.f,A2=0.f,A3=0.f;
    float B0=0.f,B1=0.f,B2=0.f,B3=0.f;
    #pragma unroll
    for (int i = 0; i < 16; i++) {
        const float* p = v + 8*i;
        A0 = __fmaf_rn(p[0], p[0], A0);
        A1 = __fmaf_rn(p[1], p[1], A1);
        A2 = __fmaf_rn(p[2], p[2], A2);
        A3 = __fmaf_rn(p[3], p[3], A3);
        B0 = __fmaf_rn(p[4], p[4], B0);
        B1 = __fmaf_rn(p[5], p[5], B1);
        B2 = __fmaf_rn(p[6], p[6], B2);
        B3 = __fmaf_rn(p[7], p[7], B3);
    }
    float S0 = __fadd_rn(A0, B0);
    float S1 = __fadd_rn(A1, B1);
    float S2 = __fadd_rn(A2, B2);
    float S3 = __fadd_rn(A3, B3);
    return __fadd_rn(__fadd_rn(S0, S1), __fadd_rn(S2, S3));
}

// exact score: single ascending-k fused-FMA chain, then rn association
__device__ __forceinline__ float exact_score(const float* __restrict__ xr,
                                             const float* __restrict__ crow,
                                             float t1, float cn) {
    float dot = 0.f;
    #pragma unroll 8
    for (int k = 0; k < DD; k += 4) {
        float4 x4 = __ldg((const float4*)(xr + k));
        float4 c4 = __ldg((const float4*)(crow + k));
        dot = __fmaf_rn(x4.x, c4.x, dot);
        dot = __fmaf_rn(x4.y, c4.y, dot);
        dot = __fmaf_rn(x4.z, c4.z, dot);
        dot = __fmaf_rn(x4.w, c4.w, dot);
    }
    return __fadd_rn(__fsub_rn(t1, __fmul_rn(2.0f, dot)), cn);
}

// ---------------------------------------------------------------------------
__global__ void k_init(const float* __restrict__ centersIn) {
    int i = blockIdx.x * blockDim.x + threadIdx.x;
    if (i < BB*CC*DD) g_centers[i] = centersIn[i];
}
__global__ void k_ptf(const float* __restrict__ data) {
    size_t i = (size_t)blockIdx.x * blockDim.x + threadIdx.x;
    if (i < (size_t)BB*NN*DD) g_ptf[i] = tf32r(data[i]);
}
__global__ void k_ctf() {
    int i = blockIdx.x * blockDim.x + threadIdx.x;
    if (i < BB*CC*DD) g_ctf[i] = tf32r(g_centers[i]);
}
__global__ void k_t1(const float* __restrict__ data) {
    int i = blockIdx.x * blockDim.x + threadIdx.x;
    if (i >= BB*NN) return;
    g_t1[i] = norm128_llvm(data + (size_t)i * DD);
}
__global__ void k_prep() {
    int i = blockIdx.x * blockDim.x + threadIdx.x;
    if (i >= BB*CC) return;
    g_cnorm[i] = norm128_llvm(g_centers + (size_t)i * DD);
}
__global__ void k_t2max() {
    __shared__ float red[CC];
    int b = blockIdx.x, t = threadIdx.x;
    red[t] = g_cnorm[b*CC + t];
    __syncthreads();
    for (int s = 256; s; s >>= 1) {
        if (t < s) red[t] = fmaxf(red[t], red[t + s]);
        __syncthreads();
    }
    if (t == 0) g_t2max[b] = red[0];
}

// ---------------------------------------------------------------------------
// Assign: TF32 mma.sync approx scores -> margin candidates -> exact refine.
// grid = (N/128, B), block = 128 (4 warps; warp w owns points 32w..32w+31).
__global__ void __launch_bounds__(128, 2) k_assign(const float* __restrict__ data) {
    extern __shared__ float sm[];
    float* ptsT = sm;                      // [128][PSTR] tf32 points
    float* cenT = ptsT + 128*PSTR;         // [64][CSTR] tf32 centers (chunk)
    float* cnS  = cenT + 64*CSTR;          // [512]
    int*   candS = (int*)(cnS + CC);       // [128 threads][16]

    const int b  = blockIdx.y;
    const int n0 = blockIdx.x * TILE_P;
    const int tid = threadIdx.x;
    const int w = tid >> 5, lane = tid & 31;
    const int g = lane >> 2, tig = lane & 3;

    for (int i = tid; i < CC; i += 128) cnS[i] = g_cnorm[b*CC + i];

    // stage tf32 point tile
    const float* ptf = g_ptf + ((size_t)b*NN + n0) * DD;
    for (int idx = tid; idx < 128*32; idx += 128) {
        int r = idx >> 5, q = idx & 31;
        float4 v = __ldg((const float4*)(ptf + (size_t)r*DD) + q);
        *(float4*)(ptsT + r*PSTR + 4*q) = v;
    }

    // this thread's 4 points (MMA row mapping): rows g, g+8 of each m-tile
    int prow[4] = {32*w + g, 32*w + g + 8, 32*w + g + 16, 32*w + g + 24};
    const float t2m = g_t2max[b];
    float t1r[4], runmin[4], thr[4], m2[4];
    int cnt[4];
    #pragma unroll
    for (int i = 0; i < 4; i++) {
        t1r[i] = g_t1[b*NN + n0 + prow[i]];
        m2[i] = 4.0f * (1.25f * 9.765625e-4f * sqrtf(t1r[i] * t2m) + 0.02f);
        runmin[i] = 3.4e38f; thr[i] = 3.4e38f; cnt[i] = 0;
    }

    const float* ctf = g_ctf + (size_t)b*CC*DD;
    const uint32_t* paB = (const uint32_t*)ptsT;
    const uint32_t* pa0 = paB + (32*w + g)*PSTR;
    const uint32_t* pa1 = paB + (32*w + g + 8)*PSTR;
    const uint32_t* pa2 = paB + (32*w + g + 16)*PSTR;
    const uint32_t* pa3 = paB + (32*w + g + 24)*PSTR;
    const uint32_t* pbg = (const uint32_t*)cenT + g*CSTR;

    for (int ch = 0; ch < 8; ch++) {
        __syncthreads();
        for (int idx = tid; idx < 64*32; idx += 128) {
            int r = idx >> 5, q = idx & 31;
            float4 v = __ldg((const float4*)(ctf + (size_t)(ch*64 + r)*DD) + q);
            *(float4*)(cenT + r*CSTR + 4*q) = v;
        }
        __syncthreads();

        float d[2][8][4];
        #pragma unroll
        for (int mt = 0; mt < 2; mt++)
            #pragma unroll
            for (int nt = 0; nt < 8; nt++)
                #pragma unroll
                for (int e = 0; e < 4; e++) d[mt][nt][e] = 0.f;

        #pragma unroll 2
        for (int ks = 0; ks < 32; ks++) {
            int k0 = 4*ks + tig;
            uint32_t a0 = pa0[k0];
            uint32_t a1 = pa1[k0];
            uint32_t a2 = pa2[k0];
            uint32_t a3 = pa3[k0];
            #pragma unroll
            for (int nt = 0; nt < 8; nt++) {
                uint32_t b0 = pbg[8*nt*CSTR + k0];
                mma_tf32_k4(d[0][nt][0], d[0][nt][1], d[0][nt][2], d[0][nt][3],
                            a0, a1, b0);
                mma_tf32_k4(d[1][nt][0], d[1][nt][1], d[1][nt][2], d[1][nt][3],
                            a2, a3, b0);
            }
        }

        // chunk epilogue: scores + candidate tracking
        #pragma unroll
        for (int nt = 0; nt < 8; nt++) {
            #pragma unroll
            for (int e = 0; e < 2; e++) {
                int cidx = ch*64 + 8*nt + 2*tig + e;
                float cn = cnS[cidx];
                #pragma unroll
                for (int mt = 0; mt < 2; mt++) {
                    #pragma unroll
                    for (int rr = 0; rr < 2; rr++) {
                        int i = 2*mt + rr;
                        float s = cn - 2.0f * d[mt][nt][2*rr + e];
                        if (s < runmin[i]) { runmin[i] = s; thr[i] = s + m2[i]; }
                        if (s <= thr[i]) {
                            if (cnt[i] < CAP) candS[tid*16 + i*4 + cnt[i]] = cidx;
                            cnt[i]++;
                        }
                    }
                }
            }
        }
    }

    // exact refine + cross-lane (tig quad) argmin reduce
    const float* db = data + ((size_t)b*NN + n0) * DD;
    const float* cb = g_centers + (size_t)b*CC*DD;
    #pragma unroll
    for (int i = 0; i < 4; i++) {
        const float* xr = db + (size_t)prow[i]*DD;
        float best = 3.4e38f;
        int bix = CC;
        if (cnt[i] <= CAP) {
            for (int j = 0; j < cnt[i]; j++) {
                int c = candS[tid*16 + i*4 + j];
                float s = exact_score(xr, cb + (size_t)c*DD, t1r[i], cnS[c]);
                if (s < best) { best = s; bix = c; }   // ascending c -> ties ok
            }
        } else {
            // overflow: exact scan of this lane's full center subset (ascending)
            for (int ch = 0; ch < 8; ch++)
                for (int nt = 0; nt < 8; nt++)
                    #pragma unroll
                    for (int e = 0; e < 2; e++) {
                        int c = ch*64 + 8*nt + 2*tig + e;
                        float s = exact_score(xr, cb + (size_t)c*DD, t1r[i], cnS[c]);
                        if (s < best) { best = s; bix = c; }
                    }
        }
        #pragma unroll
        for (int off = 1; off <= 2; off <<= 1) {
            float ov = __shfl_xor_sync(0xffffffffu, best, off);
            int   oi = __shfl_xor_sync(0xffffffffu, bix, off);
            if (ov < best || (ov == best && oi < bix)) { best = ov; bix = oi; }
        }
        if (tig == 0) g_assign[b*NN + n0 + prow[i]] = bix;
    }
}

// ---------------------------------------------------------------------------
// Stable counting sort of points by cluster (ascending n within cluster).
__global__ void k_sort() {
    __shared__ int hist[CC];
    __shared__ int cursor[CC];
    __shared__ int wt[CC];
    extern __shared__ int W[];   // [32 warps][CC]

    int b = blockIdx.x, tid = threadIdx.x;
    int w = tid >> 5, lane = tid & 31;

    for (int i = tid; i < CC; i += 1024) hist[i] = 0;
    __syncthreads();
    for (int n = tid; n < NN; n += 1024)
        atomicAdd(&hist[g_assign[b*NN + n]], 1);
    __syncthreads();
    if (tid == 0) {
        int run = 0;
        for (int c = 0; c < CC; c++) {
            cursor[c] = run;
            g_off[b*CC + c] = run;
            int h = hist[c];
            g_cnt[b*CC + c] = h;
            run += h;
        }
    }
    __syncthreads();

    for (int wave = 0; wave < NN/1024; wave++) {
        for (int i = tid; i < 32*CC; i += 1024) W[i] = 0;
        __syncthreads();
        int n = wave*1024 + tid;
        int a = g_assign[b*NN + n];
        unsigned mask = __match_any_sync(0xffffffffu, a);
        int rank = __popc(mask & ((1u << lane) - 1u));
        if (rank == 0) W[w*CC + a] = __popc(mask);
        __syncthreads();
        if (tid < CC) {
            int s = 0;
            for (int ww = 0; ww < 32; ww++) {
                int t = W[ww*CC + tid];
                W[ww*CC + tid] = s;
                s += t;
            }
            wt[tid] = s;
        }
        __syncthreads();
        int pos = cursor[a] + W[w*CC + a] + rank;
        g_list[b*NN + pos] = n;
        __syncthreads();
        if (tid < CC) cursor[tid] += wt[tid];
        __syncthreads();
    }
}

// ---------------------------------------------------------------------------
// New centers: sequential ascending-n fp32 adds per (b,c,d), then rn divide.
__global__ void k_update(const float* __restrict__ data) {
    __shared__ int listS[128];
    int c = blockIdx.x, b = blockIdx.y, d = threadIdx.x;
    int off = g_off[b*CC + c];
    int cnt = g_cnt[b*CC + c];
    float acc = 0.f;
    for (int base = 0; base < cnt; base += 128) {
        __syncthreads();
        int m = min(128, cnt - base);
        if (d < m) listS[d] = g_list[b*NN + off + base + d];
        __syncthreads();
        for (int j = 0; j < m; j++) {
            int n = listS[j];
            acc = __fadd_rn(acc, __ldg(&data[((size_t)b*NN + n)*DD + d]));
        }
    }
    if (cnt > 0)
        g_centers[(size_t)(b*CC + c)*DD + d] = __fdiv_rn(acc, __int2float_rn(cnt));
}

// d_out = [centers (B*C*D) | (float)assign broadcast over D (B*N*D)]
__global__ void k_output(float* __restrict__ out) {
    size_t i = (size_t)blockIdx.x * blockDim.x + threadIdx.x;
    const size_t nc = (size_t)BB*CC*DD;
    const size_t total = nc + (size_t)BB*NN*DD;
    if (i >= total) return;
    if (i < nc) out[i] = g_centers[i];
    else {
        size_t j = i - nc;
        out[i] = (float)g_assign[j >> 7];
    }
}

// ---------------------------------------------------------------------------
extern "C" void kernel_launch(void* const* d_in, const int* in_sizes, int n_in,
                              void* d_out, int out_size) {
    const float* data      = (const float*)d_in[0];
    const float* centersIn = (const float*)d_in[1];
    float* out = (float*)d_out;

    cudaFuncSetAttribute(k_assign, cudaFuncAttributeMaxDynamicSharedMemorySize,
                         SMEM_BYTES);
    cudaFuncSetAttribute(k_sort, cudaFuncAttributeMaxDynamicSharedMemorySize,
                         32*CC*(int)sizeof(int));

    k_init<<<(BB*CC*DD + 255)/256, 256>>>(centersIn);
    k_t1<<<(BB*NN + 255)/256, 256>>>(data);
    {
        size_t tot = (size_t)BB*NN*DD;
        k_ptf<<<(unsigned)((tot + 255)/256), 256>>>(data);
    }
    for (int it = 0; it < ITERS; it++) {
        k_prep<<<(BB*CC + 255)/256, 256>>>();
        k_t2max<<<BB, 512>>>();
        k_ctf<<<(BB*CC*DD + 255)/256, 256>>>();
        k_assign<<<dim3(NN/TILE_P, BB), 128, SMEM_BYTES>>>(data);
        k_sort<<<BB, 1024, 32*CC*(int)sizeof(int)>>>();
        k_update<<<dim3(CC, BB), 128>>>(data);
    }
    const size_t total = (size_t)BB*CC*DD + (size_t)BB*NN*DD;
    k_output<<<(unsigned)((total + 255)/256), 256>>>(out);
}

// round 8
// speedup vs baseline: 1.2857x; 1.2857x over previous
#include <cuda_runtime.h>
#include <cstdint>

#define BB 8
#define NN 65536
#define CC 512
#define DD 128
#define ITERS 10
#define TILE_P 128
#define CAP 4

#define PSTR 132   // floats per tf32-point row (132 % 32 == 4 -> conflict-free)
#define CSTR 132   // floats per tf32-center row

// smem floats: ptsT 128*132, cenT 64*132, cn 512, cand 128*16 ints
#define SMEM_FLOATS (128*PSTR + 64*CSTR + CC + 128*16)
#define SMEM_BYTES  (SMEM_FLOATS * 4)

__device__ float g_centers[BB*CC*DD];
__device__ float g_ctf[BB*CC*DD];        // tf32-rounded centers (per iter)
__device__ float g_ptf[BB*NN*DD];        // tf32-rounded points (once)
__device__ float g_cnorm[BB*CC];
__device__ float g_t2max[BB];
__device__ float g_t1[BB*NN];
__device__ int   g_assign[BB*NN];
__device__ int   g_list[BB*NN];
__device__ int   g_off[BB*CC];
__device__ int   g_cnt[BB*CC];

__device__ __forceinline__ float tf32r(float x) {
    uint32_t u;
    asm("cvt.rna.tf32.f32 %0, %1;" : "=r"(u) : "f"(x));
    return __uint_as_float(u);
}
__device__ __forceinline__ void mma_tf32_k4(float& d0, float& d1, float& d2,
                                            float& d3, uint32_t a0, uint32_t a1,
                                            uint32_t b0) {
    asm volatile(
        "mma.sync.aligned.m16n8k4.row.col.f32.tf32.tf32.f32 "
        "{%0,%1,%2,%3}, {%4,%5}, {%6}, {%0,%1,%2,%3};"
        : "+f"(d0), "+f"(d1), "+f"(d2), "+f"(d3)
        : "r"(a0), "r"(a1), "r"(b0));
}

// ---------------- exact-arithmetic building blocks (DO NOT REORDER) --------
// LLVM-style vectorized sum of v[k]^2: VF=4, IC=2, fma, lanewise, faddp.
__device__ __forceinline__ float norm128_llvm(const float* __restrict__ v) {
    float A0=0.f,A1=0.f,A2=0.f,A3=0.f;
    float B0=0.f,B1=0.f,B2=0.f,B3=0.f;
    #pragma unroll
    for (int i = 0; i < 16; i++) {
        const float* p = v + 8*i;
        A0 = __fmaf_rn(p[0], p[0], A0);
        A1 = __fmaf_rn(p[1], p[1], A1);
        A2 = __fmaf_rn(p[2], p[2], A2);
        A3 = __fmaf_rn(p[3], p[3], A3);
        B0 = __fmaf_rn(p[4], p[4], B0);
        B1 = __fmaf_rn(p[5], p[5], B1);
        B2 = __fmaf_rn(p[6], p[6], B2);
        B3 = __fmaf_rn(p[7], p[7], B3);
    }
    float S0 = __fadd_rn(A0, B0);
    float S1 = __fadd_rn(A1, B1);
    float S2 = __fadd_rn(A2, B2);
    float S3 = __fadd_rn(A3, B3);
    return __fadd_rn(__fadd_rn(S0, S1), __fadd_rn(S2, S3));
}

// exact score: single ascending-k fused-FMA chain, then rn association
__device__ __forceinline__ float exact_score(const float* __restrict__ xr,
                                             const float* __restrict__ crow,
                                             float t1, float cn) {
    float dot = 0.f;
    #pragma unroll 8
    for (int k = 0; k < DD; k += 4) {
        float4 x4 = __ldg((const float4*)(xr + k));
        float4 c4 = __ldg((const float4*)(crow + k));
        dot = __fmaf_rn(x4.x, c4.x, dot);
        dot = __fmaf_rn(x4.y, c4.y, dot);
        dot = __fmaf_rn(x4.z, c4.z, dot);
        dot = __fmaf_rn(x4.w, c4.w, dot);
    }
    return __fadd_rn(__fsub_rn(t1, __fmul_rn(2.0f, dot)), cn);
}

// ---------------------------------------------------------------------------
__global__ void k_init(const float* __restrict__ centersIn) {
    int i = blockIdx.x * blockDim.x + threadIdx.x;
    if (i < BB*CC*DD) g_centers[i] = centersIn[i];
}
__global__ void k_ptf(const float* __restrict__ data) {
    size_t i = (size_t)blockIdx.x * blockDim.x + threadIdx.x;
    if (i < (size_t)BB*NN*DD) g_ptf[i] = tf32r(data[i]);
}
__global__ void k_ctf() {
    int i = blockIdx.x * blockDim.x + threadIdx.x;
    if (i < BB*CC*DD) g_ctf[i] = tf32r(g_centers[i]);
}
__global__ void k_t1(const float* __restrict__ data) {
    int i = blockIdx.x * blockDim.x + threadIdx.x;
    if (i >= BB*NN) return;
    g_t1[i] = norm128_llvm(data + (size_t)i * DD);
}
__global__ void k_prep() {
    int i = blockIdx.x * blockDim.x + threadIdx.x;
    if (i >= BB*CC) return;
    g_cnorm[i] = norm128_llvm(g_centers + (size_t)i * DD);
}
__global__ void k_t2max() {
    __shared__ float red[CC];
    int b = blockIdx.x, t = threadIdx.x;
    red[t] = g_cnorm[b*CC + t];
    __syncthreads();
    for (int s = 256; s; s >>= 1) {
        if (t < s) red[t] = fmaxf(red[t], red[t + s]);
        __syncthreads();
    }
    if (t == 0) g_t2max[b] = red[0];
}

// ---------------------------------------------------------------------------
// Assign: TF32 mma.sync approx scores -> margin candidates -> exact refine.
// grid = (N/128, B), block = 128 (4 warps; warp w owns points 32w..32w+31).
__global__ void __launch_bounds__(128, 2) k_assign(const float* __restrict__ data) {
    extern __shared__ float sm[];
    float* ptsT = sm;                      // [128][PSTR] tf32 points
    float* cenT = ptsT + 128*PSTR;         // [64][CSTR] tf32 centers (chunk)
    float* cnS  = cenT + 64*CSTR;          // [512]
    int*   candS = (int*)(cnS + CC);       // [128 threads][16]

    const int b  = blockIdx.y;
    const int n0 = blockIdx.x * TILE_P;
    const int tid = threadIdx.x;
    const int w = tid >> 5, lane = tid & 31;
    const int g = lane >> 2, tig = lane & 3;

    for (int i = tid; i < CC; i += 128) cnS[i] = g_cnorm[b*CC + i];

    // stage tf32 point tile
    const float* ptf = g_ptf + ((size_t)b*NN + n0) * DD;
    for (int idx = tid; idx < 128*32; idx += 128) {
        int r = idx >> 5, q = idx & 31;
        float4 v = __ldg((const float4*)(ptf + (size_t)r*DD) + q);
        *(float4*)(ptsT + r*PSTR + 4*q) = v;
    }

    // this thread's 4 points (MMA row mapping): rows g, g+8 of each m-tile
    int prow[4] = {32*w + g, 32*w + g + 8, 32*w + g + 16, 32*w + g + 24};
    const float t2m = g_t2max[b];
    float t1r[4], runmin[4], thr[4], m2[4];
    int cnt[4];
    #pragma unroll
    for (int i = 0; i < 4; i++) {
        t1r[i] = g_t1[b*NN + n0 + prow[i]];
        // window = 2M; M = 1.1*2*2^-11*sqrt(t1*t2max) + 0.01  (tf32 rounding
        // on both operands + fp32 reorder slop). Provable superset margin.
        m2[i] = 2.0f * (1.1f * 9.765625e-4f * sqrtf(t1r[i] * t2m) + 0.01f);
        runmin[i] = 3.4e38f; thr[i] = 3.4e38f; cnt[i] = 0;
    }

    const float* ctf = g_ctf + (size_t)b*CC*DD;
    const uint32_t* paB = (const uint32_t*)ptsT;
    const uint32_t* pa0 = paB + (32*w + g)*PSTR;
    const uint32_t* pa1 = paB + (32*w + g + 8)*PSTR;
    const uint32_t* pa2 = paB + (32*w + g + 16)*PSTR;
    const uint32_t* pa3 = paB + (32*w + g + 24)*PSTR;
    const uint32_t* pbg = (const uint32_t*)cenT + g*CSTR;

    for (int ch = 0; ch < 8; ch++) {
        __syncthreads();
        for (int idx = tid; idx < 64*32; idx += 128) {
            int r = idx >> 5, q = idx & 31;
            float4 v = __ldg((const float4*)(ctf + (size_t)(ch*64 + r)*DD) + q);
            *(float4*)(cenT + r*CSTR + 4*q) = v;
        }
        __syncthreads();

        float d[2][8][4];
        #pragma unroll
        for (int mt = 0; mt < 2; mt++)
            #pragma unroll
            for (int nt = 0; nt < 8; nt++)
                #pragma unroll
                for (int e = 0; e < 4; e++) d[mt][nt][e] = 0.f;

        #pragma unroll 2
        for (int ks = 0; ks < 32; ks++) {
            int k0 = 4*ks + tig;
            uint32_t a0 = pa0[k0];
            uint32_t a1 = pa1[k0];
            uint32_t a2 = pa2[k0];
            uint32_t a3 = pa3[k0];
            #pragma unroll
            for (int nt = 0; nt < 8; nt++) {
                uint32_t b0 = pbg[8*nt*CSTR + k0];
                mma_tf32_k4(d[0][nt][0], d[0][nt][1], d[0][nt][2], d[0][nt][3],
                            a0, a1, b0);
                mma_tf32_k4(d[1][nt][0], d[1][nt][1], d[1][nt][2], d[1][nt][3],
                            a2, a3, b0);
            }
        }

        // chunk epilogue: scores + candidate tracking (thr only decreases ->
        // appended set is always a superset of the final-threshold set)
        #pragma unroll
        for (int nt = 0; nt < 8; nt++) {
            #pragma unroll
            for (int e = 0; e < 2; e++) {
                int cidx = ch*64 + 8*nt + 2*tig + e;
                float cn = cnS[cidx];
                #pragma unroll
                for (int mt = 0; mt < 2; mt++) {
                    #pragma unroll
                    for (int rr = 0; rr < 2; rr++) {
                        int i = 2*mt + rr;
                        float s = cn - 2.0f * d[mt][nt][2*rr + e];
                        if (s < runmin[i]) {
                            runmin[i] = s;
                            thr[i] = fminf(thr[i], s + m2[i]);
                        }
                        if (s <= thr[i]) {
                            if (cnt[i] < CAP) candS[tid*16 + i*4 + cnt[i]] = cidx;
                            cnt[i]++;
                        }
                    }
                }
            }
        }

        // cross-lane tightening: the 4 tig-lanes of a quad partition this
        // point's centers; share the global running min to shrink thresholds
        #pragma unroll
        for (int i = 0; i < 4; i++) {
            float q = runmin[i];
            q = fminf(q, __shfl_xor_sync(0xffffffffu, q, 1));
            q = fminf(q, __shfl_xor_sync(0xffffffffu, q, 2));
            thr[i] = fminf(thr[i], q + m2[i]);
        }
    }

    // exact refine + cross-lane (tig quad) argmin reduce
    const float* db = data + ((size_t)b*NN + n0) * DD;
    const float* cb = g_centers + (size_t)b*CC*DD;
    #pragma unroll
    for (int i = 0; i < 4; i++) {
        const float* xr = db + (size_t)prow[i]*DD;
        float best = 3.4e38f;
        int bix = CC;
        if (cnt[i] <= CAP) {
            for (int j = 0; j < cnt[i]; j++) {
                int c = candS[tid*16 + i*4 + j];
                float s = exact_score(xr, cb + (size_t)c*DD, t1r[i], cnS[c]);
                if (s < best) { best = s; bix = c; }   // ascending c -> ties ok
            }
        } else {
            // overflow (rare): exact scan of this lane's center subset
            for (int ch = 0; ch < 8; ch++)
                for (int nt = 0; nt < 8; nt++)
                    #pragma unroll
                    for (int e = 0; e < 2; e++) {
                        int c = ch*64 + 8*nt + 2*tig + e;
                        float s = exact_score(xr, cb + (size_t)c*DD, t1r[i], cnS[c]);
                        if (s < best) { best = s; bix = c; }
                    }
        }
        #pragma unroll
        for (int off = 1; off <= 2; off <<= 1) {
            float ov = __shfl_xor_sync(0xffffffffu, best, off);
            int   oi = __shfl_xor_sync(0xffffffffu, bix, off);
            if (ov < best || (ov == best && oi < bix)) { best = ov; bix = oi; }
        }
        if (tig == 0) g_assign[b*NN + n0 + prow[i]] = bix;
    }
}

// ---------------------------------------------------------------------------
// Stable counting sort of points by cluster (ascending n within cluster).
__global__ void k_sort() {
    __shared__ int hist[CC];
    __shared__ int cursor[CC];
    __shared__ int wt[CC];
    extern __shared__ int W[];   // [32 warps][CC]

    int b = blockIdx.x, tid = threadIdx.x;
    int w = tid >> 5, lane = tid & 31;

    for (int i = tid; i < CC; i += 1024) hist[i] = 0;
    __syncthreads();
    for (int n = tid; n < NN; n += 1024)
        atomicAdd(&hist[g_assign[b*NN + n]], 1);
    __syncthreads();
    if (tid == 0) {
        int run = 0;
        for (int c = 0; c < CC; c++) {
            cursor[c] = run;
            g_off[b*CC + c] = run;
            int h = hist[c];
            g_cnt[b*CC + c] = h;
            run += h;
        }
    }
    __syncthreads();

    for (int wave = 0; wave < NN/1024; wave++) {
        for (int i = tid; i < 32*CC; i += 1024) W[i] = 0;
        __syncthreads();
        int n = wave*1024 + tid;
        int a = g_assign[b*NN + n];
        unsigned mask = __match_any_sync(0xffffffffu, a);
        int rank = __popc(mask & ((1u << lane) - 1u));
        if (rank == 0) W[w*CC + a] = __popc(mask);
        __syncthreads();
        if (tid < CC) {
            int s = 0;
            for (int ww = 0; ww < 32; ww++) {
                int t = W[ww*CC + tid];
                W[ww*CC + tid] = s;
                s += t;
            }
            wt[tid] = s;
        }
        __syncthreads();
        int pos = cursor[a] + W[w*CC + a] + rank;
        g_list[b*NN + pos] = n;
        __syncthreads();
        if (tid < CC) cursor[tid] += wt[tid];
        __syncthreads();
    }
}

// ---------------------------------------------------------------------------
// New centers: sequential ascending-n fp32 adds per (b,c,d), then rn divide.
__global__ void k_update(const float* __restrict__ data) {
    __shared__ int listS[128];
    int c = blockIdx.x, b = blockIdx.y, d = threadIdx.x;
    int off = g_off[b*CC + c];
    int cnt = g_cnt[b*CC + c];
    float acc = 0.f;
    for (int base = 0; base < cnt; base += 128) {
        __syncthreads();
        int m = min(128, cnt - base);
        if (d < m) listS[d] = g_list[b*NN + off + base + d];
        __syncthreads();
        for (int j = 0; j < m; j++) {
            int n = listS[j];
            acc = __fadd_rn(acc, __ldg(&data[((size_t)b*NN + n)*DD + d]));
        }
    }
    if (cnt > 0)
        g_centers[(size_t)(b*CC + c)*DD + d] = __fdiv_rn(acc, __int2float_rn(cnt));
}

// d_out = [centers (B*C*D) | (float)assign broadcast over D (B*N*D)]
__global__ void k_output(float* __restrict__ out) {
    size_t i = (size_t)blockIdx.x * blockDim.x + threadIdx.x;
    const size_t nc = (size_t)BB*CC*DD;
    const size_t total = nc + (size_t)BB*NN*DD;
    if (i >= total) return;
    if (i < nc) out[i] = g_centers[i];
    else {
        size_t j = i - nc;
        out[i] = (float)g_assign[j >> 7];
    }
}

// ---------------------------------------------------------------------------
extern "C" void kernel_launch(void* const* d_in, const int* in_sizes, int n_in,
                              void* d_out, int out_size) {
    const float* data      = (const float*)d_in[0];
    const float* centersIn = (const float*)d_in[1];
    float* out = (float*)d_out;

    cudaFuncSetAttribute(k_assign, cudaFuncAttributeMaxDynamicSharedMemorySize,
                         SMEM_BYTES);
    cudaFuncSetAttribute(k_sort, cudaFuncAttributeMaxDynamicSharedMemorySize,
                         32*CC*(int)sizeof(int));

    k_init<<<(BB*CC*DD + 255)/256, 256>>>(centersIn);
    k_t1<<<(BB*NN + 255)/256, 256>>>(data);
    {
        size_t tot = (size_t)BB*NN*DD;
        k_ptf<<<(unsigned)((tot + 255)/256), 256>>>(data);
    }
    for (int it = 0; it < ITERS; it++) {
        k_prep<<<(BB*CC + 255)/256, 256>>>();
        k_t2max<<<BB, 512>>>();
        k_ctf<<<(BB*CC*DD + 255)/256, 256>>>();
        k_assign<<<dim3(NN/TILE_P, BB), 128, SMEM_BYTES>>>(data);
        k_sort<<<BB, 1024, 32*CC*(int)sizeof(int)>>>();
        k_update<<<dim3(CC, BB), 128>>>(data);
    }
    const size_t total = (size_t)BB*CC*DD + (size_t)BB*NN*DD;
    k_output<<<(unsigned)((total + 255)/256), 256>>>(out);
}

// round 9
// speedup vs baseline: 11.7235x; 9.1185x over previous
#include <cuda_runtime.h>
#include <cstdint>

#define BB 8
#define NN 65536
#define CC 512
#define DD 128
#define ITERS 10
#define TILE_P 128
#define QSTRIDE 516            // words per point-quad row (bank-staggered)
#define CROW 128               // words per k-row of dup'd 64-center chunk

// smem: points 32*516, two 64KB center buffers, cnorm 512
#define SMEM_BYTES ((32*QSTRIDE + 2*128*CROW + CC) * 4)

__device__ float g_centers[BB*CC*DD];
__device__ float g_cTd[BB*8*DD*CROW];   // [b][chunk64][k][slot] dup'd centers
__device__ float g_cnorm[BB*CC];
__device__ float g_t1[BB*NN];
__device__ int   g_assign[BB*NN];
__device__ int   g_list[BB*NN];
__device__ int   g_off[BB*CC];
__device__ int   g_cnt[BB*CC];

__device__ __forceinline__ void fma2(unsigned long long &d,
                                     unsigned long long a,
                                     unsigned long long b) {
    asm("fma.rn.f32x2 %0, %1, %2, %0;" : "+l"(d) : "l"(a), "l"(b));
}
__device__ __forceinline__ uint32_t smem_u32(const void* p) {
    uint32_t a;
    asm("{ .reg .u64 t; cvta.to.shared.u64 t, %1; cvt.u32.u64 %0, t; }"
        : "=r"(a) : "l"(p));
    return a;
}
__device__ __forceinline__ void cp16(uint32_t dsmem, const void* gsrc) {
    asm volatile("cp.async.cg.shared.global [%0], [%1], 16;"
                 :: "r"(dsmem), "l"(gsrc));
}
#define CP_COMMIT() asm volatile("cp.async.commit_group;" ::: "memory")
#define CP_WAIT0()  asm volatile("cp.async.wait_group 0;" ::: "memory")

// ---------------- exact-arithmetic building blocks (DO NOT REORDER) --------
// LLVM-style vectorized sum of v[k]^2: VF=4, IC=2, fma, lanewise, faddp.
__device__ __forceinline__ float norm128_llvm(const float* __restrict__ v) {
    float A0=0.f,A1=0.f,A2=0.f,A3=0.f;
    float B0=0.f,B1=0.f,B2=0.f,B3=0.f;
    #pragma unroll
    for (int i = 0; i < 16; i++) {
        const float* p = v + 8*i;
        A0 = __fmaf_rn(p[0], p[0], A0);
        A1 = __fmaf_rn(p[1], p[1], A1);
        A2 = __fmaf_rn(p[2], p[2], A2);
        A3 = __fmaf_rn(p[3], p[3], A3);
        B0 = __fmaf_rn(p[4], p[4], B0);
        B1 = __fmaf_rn(p[5], p[5], B1);
        B2 = __fmaf_rn(p[6], p[6], B2);
        B3 = __fmaf_rn(p[7], p[7], B3);
    }
    float S0 = __fadd_rn(A0, B0);
    float S1 = __fadd_rn(A1, B1);
    float S2 = __fadd_rn(A2, B2);
    float S3 = __fadd_rn(A3, B3);
    return __fadd_rn(__fadd_rn(S0, S1), __fadd_rn(S2, S3));
}

// ---------------------------------------------------------------------------
__global__ void k_init(const float* __restrict__ centersIn) {
    int i = blockIdx.x * blockDim.x + threadIdx.x;
    if (i < BB*CC*DD) g_centers[i] = centersIn[i];
}
__global__ void k_t1(const float* __restrict__ data) {
    int i = blockIdx.x * blockDim.x + threadIdx.x;
    if (i >= BB*NN) return;
    g_t1[i] = norm128_llvm(data + (size_t)i * DD);
}
__global__ void k_prep() {
    int i = blockIdx.x * blockDim.x + threadIdx.x;
    if (i >= BB*CC) return;
    g_cnorm[i] = norm128_llvm(g_centers + (size_t)i * DD);
}

// dup'd k-major chunk layout: center c (0..63) -> slot = (c>>4)*32 +
// ((c&15)>>1)*4 + (c&1)*2  (+d for the duplicate)
__global__ void k_transpose() {
    int i = blockIdx.x * blockDim.x + threadIdx.x;
    if (i >= BB*8*DD*64) return;
    int c  = i & 63;
    int k  = (i >> 6) & 127;
    int ch = (i >> 13) & 7;
    int b  = i >> 16;
    float v = g_centers[((size_t)(b*CC + ch*64 + c))*DD + k];
    int slot = ((c >> 4) << 5) + (((c & 15) >> 1) << 2) + ((c & 1) << 1);
    float2* dst = (float2*)(g_cTd + ((size_t)((b*8 + ch)*DD + k))*CROW + slot);
    *dst = make_float2(v, v);
}

// ---------------------------------------------------------------------------
// Assign: exact fp32 fma2 chains, all 512 centers, cp.async double-buffered.
// grid = (N/128, B), block = 128. Thread: 8 points (8pg..) x 8 centers.
__global__ void __launch_bounds__(128, 1) k_assign(const float* __restrict__ data) {
    extern __shared__ float sm[];
    float* ptsS = sm;                       // [32 quads][QSTRIDE]
    float* cenB0 = ptsS + 32*QSTRIDE;       // buffer 0: [128 k][CROW]
    float* cenB1 = cenB0 + 128*CROW;        // buffer 1
    float* cnS  = cenB1 + 128*CROW;         // [512]

    const int b  = blockIdx.y;
    const int n0 = blockIdx.x * TILE_P;
    const int tid = threadIdx.x;
    const int pg = tid >> 3;   // 0..15 : points 8pg..8pg+7
    const int cg = tid & 7;    // 0..7  : centers {16i + 2cg + e}

    for (int i = tid; i < CC; i += 128) cnS[i] = g_cnorm[b*CC + i];

    // point tile, quad-packed: ptsS[p>>2][4k + (p&3)] = x_p[k]
    const float* dptr = data + ((size_t)b*NN + n0) * DD;
    for (int idx = tid; idx < TILE_P*32; idx += 128) {
        int p = idx & 127;
        int q = idx >> 7;
        float4 v = __ldg((const float4*)(dptr + (size_t)p*DD) + q);
        float* dst = ptsS + (p >> 2)*QSTRIDE + (p & 3);
        int k4 = q * 4;
        dst[(k4+0)*4] = v.x; dst[(k4+1)*4] = v.y;
        dst[(k4+2)*4] = v.z; dst[(k4+3)*4] = v.w;
    }

    float t1r[8];
    #pragma unroll
    for (int i = 0; i < 8; i++) t1r[i] = g_t1[b*NN + n0 + 8*pg + i];

    float bv[8]; int bi[8];
    #pragma unroll
    for (int i = 0; i < 8; i++) { bv[i] = 3.4e38f; bi[i] = 0; }

    const char* csrc = (const char*)(g_cTd + (size_t)b*8*DD*CROW);
    const uint32_t sb0 = smem_u32(cenB0);
    const uint32_t sb1 = smem_u32(cenB1);

    // prefetch chunk 0 into buffer 0
    #pragma unroll
    for (int j = 0; j < 32; j++)
        cp16(sb0 + j*2048 + tid*16, csrc + j*2048 + tid*16);
    CP_COMMIT();

    const float* q0p = ptsS + (2*pg)*QSTRIDE;
    const float* q1p = q0p + QSTRIDE;

    for (int ch = 0; ch < 8; ch++) {
        CP_WAIT0();
        __syncthreads();   // chunk ch arrived; prior compute done

        if (ch < 7) {      // prefetch ch+1 into the other buffer
            uint32_t nb = ((ch + 1) & 1) ? sb1 : sb0;
            const char* src = csrc + (size_t)(ch + 1)*DD*CROW*4;
            #pragma unroll
            for (int j = 0; j < 32; j++)
                cp16(nb + j*2048 + tid*16, src + j*2048 + tid*16);
            CP_COMMIT();
        }

        const float* cw = ((ch & 1) ? cenB1 : cenB0) + 4*cg;

        unsigned long long acc[4][8];   // [point pair][center j=2i+e]
        #pragma unroll
        for (int q = 0; q < 4; q++)
            #pragma unroll
            for (int j = 0; j < 8; j++) acc[q][j] = 0ull;

        #pragma unroll 4
        for (int k = 0; k < DD; k++) {
            ulonglong2 Q0 = *(const ulonglong2*)(q0p + 4*k);
            ulonglong2 Q1 = *(const ulonglong2*)(q1p + 4*k);
            const float* ck = cw + k*CROW;
            #pragma unroll
            for (int i = 0; i < 4; i++) {
                ulonglong2 C = *(const ulonglong2*)(ck + i*32);
                fma2(acc[0][2*i],   Q0.x, C.x); fma2(acc[1][2*i],   Q0.y, C.x);
                fma2(acc[2][2*i],   Q1.x, C.x); fma2(acc[3][2*i],   Q1.y, C.x);
                fma2(acc[0][2*i+1], Q0.x, C.y); fma2(acc[1][2*i+1], Q0.y, C.y);
                fma2(acc[2][2*i+1], Q1.x, C.y); fma2(acc[3][2*i+1], Q1.y, C.y);
            }
        }

        // epilogue: s = (t1 - 2*dot) + cn, rn ops in reference association
        int c0 = ch * 64;
        #pragma unroll
        for (int i = 0; i < 4; i++) {
            #pragma unroll
            for (int e = 0; e < 2; e++) {
                int cidx = c0 + 16*i + 2*cg + e;
                float cn = cnS[cidx];
                #pragma unroll
                for (int q = 0; q < 4; q++) {
                    float2 f = *(float2*)&acc[q][2*i + e];
                    float slo = __fadd_rn(__fsub_rn(t1r[2*q],
                                          __fmul_rn(2.0f, f.x)), cn);
                    float shi = __fadd_rn(__fsub_rn(t1r[2*q+1],
                                          __fmul_rn(2.0f, f.y)), cn);
                    if (slo < bv[2*q])   { bv[2*q]   = slo; bi[2*q]   = cidx; }
                    if (shi < bv[2*q+1]) { bv[2*q+1] = shi; bi[2*q+1] = cidx; }
                }
            }
        }
    }

    // argmin across the 8 cg-lanes per point (tie -> lowest index)
    #pragma unroll
    for (int i = 0; i < 8; i++) {
        float v = bv[i]; int ix = bi[i];
        #pragma unroll
        for (int off = 1; off <= 4; off <<= 1) {
            float ov = __shfl_xor_sync(0xffffffffu, v, off);
            int   oi = __shfl_xor_sync(0xffffffffu, ix, off);
            if (ov < v || (ov == v && oi < ix)) { v = ov; ix = oi; }
        }
        if (cg == 0) g_assign[b*NN + n0 + 8*pg + i] = ix;
    }
}

// ---------------------------------------------------------------------------
// Stable counting sort of points by cluster (ascending n within cluster).
__global__ void k_sort() {
    __shared__ int hist[CC];
    __shared__ int cursor[CC];
    __shared__ int wt[CC];
    extern __shared__ int W[];   // [32 warps][CC]

    int b = blockIdx.x, tid = threadIdx.x;
    int w = tid >> 5, lane = tid & 31;

    for (int i = tid; i < CC; i += 1024) hist[i] = 0;
    __syncthreads();
    for (int n = tid; n < NN; n += 1024)
        atomicAdd(&hist[g_assign[b*NN + n]], 1);
    __syncthreads();
    if (tid == 0) {
        int run = 0;
        for (int c = 0; c < CC; c++) {
            cursor[c] = run;
            g_off[b*CC + c] = run;
            int h = hist[c];
            g_cnt[b*CC + c] = h;
            run += h;
        }
    }
    __syncthreads();

    for (int wave = 0; wave < NN/1024; wave++) {
        for (int i = tid; i < 32*CC; i += 1024) W[i] = 0;
        __syncthreads();
        int n = wave*1024 + tid;
        int a = g_assign[b*NN + n];
        unsigned mask = __match_any_sync(0xffffffffu, a);
        int rank = __popc(mask & ((1u << lane) - 1u));
        if (rank == 0) W[w*CC + a] = __popc(mask);
        __syncthreads();
        if (tid < CC) {
            int s = 0;
            for (int ww = 0; ww < 32; ww++) {
                int t = W[ww*CC + tid];
                W[ww*CC + tid] = s;
                s += t;
            }
            wt[tid] = s;
        }
        __syncthreads();
        int pos = cursor[a] + W[w*CC + a] + rank;
        g_list[b*NN + pos] = n;
        __syncthreads();
        if (tid < CC) cursor[tid] += wt[tid];
        __syncthreads();
    }
}

// ---------------------------------------------------------------------------
// New centers: sequential ascending-n fp32 adds per (b,c,d), then rn divide.
// Unrolled x8: loads batched (independent), adds strictly in ascending order.
__global__ void k_update(const float* __restrict__ data) {
    __shared__ int listS[128];
    int c = blockIdx.x, b = blockIdx.y, d = threadIdx.x;
    int off = g_off[b*CC + c];
    int cnt = g_cnt[b*CC + c];
    const float* db = data + (size_t)b*NN*DD + d;
    float acc = 0.f;
    for (int base = 0; base < cnt; base += 128) {
        __syncthreads();
        int m = min(128, cnt - base);
        if (d < m) listS[d] = g_list[b*NN + off + base + d];
        __syncthreads();
        int j = 0;
        for (; j + 8 <= m; j += 8) {
            float v0 = __ldg(db + (size_t)listS[j+0]*DD);
            float v1 = __ldg(db + (size_t)listS[j+1]*DD);
            float v2 = __ldg(db + (size_t)listS[j+2]*DD);
            float v3 = __ldg(db + (size_t)listS[j+3]*DD);
            float v4 = __ldg(db + (size_t)listS[j+4]*DD);
            float v5 = __ldg(db + (size_t)listS[j+5]*DD);
            float v6 = __ldg(db + (size_t)listS[j+6]*DD);
            float v7 = __ldg(db + (size_t)listS[j+7]*DD);
            acc = __fadd_rn(acc, v0); acc = __fadd_rn(acc, v1);
            acc = __fadd_rn(acc, v2); acc = __fadd_rn(acc, v3);
            acc = __fadd_rn(acc, v4); acc = __fadd_rn(acc, v5);
            acc = __fadd_rn(acc, v6); acc = __fadd_rn(acc, v7);
        }
        for (; j < m; j++)
            acc = __fadd_rn(acc, __ldg(db + (size_t)listS[j]*DD));
    }
    if (cnt > 0)
        g_centers[(size_t)(b*CC + c)*DD + d] = __fdiv_rn(acc, __int2float_rn(cnt));
}

// d_out = [centers (B*C*D) | (float)assign broadcast over D (B*N*D)]
__global__ void k_output(float* __restrict__ out) {
    size_t i = (size_t)blockIdx.x * blockDim.x + threadIdx.x;
    const size_t nc = (size_t)BB*CC*DD;
    const size_t total = nc + (size_t)BB*NN*DD;
    if (i >= total) return;
    if (i < nc) out[i] = g_centers[i];
    else {
        size_t j = i - nc;
        out[i] = (float)g_assign[j >> 7];
    }
}

// ---------------------------------------------------------------------------
extern "C" void kernel_launch(void* const* d_in, const int* in_sizes, int n_in,
                              void* d_out, int out_size) {
    const float* data      = (const float*)d_in[0];
    const float* centersIn = (const float*)d_in[1];
    float* out = (float*)d_out;

    cudaFuncSetAttribute(k_assign, cudaFuncAttributeMaxDynamicSharedMemorySize,
                         SMEM_BYTES);
    cudaFuncSetAttribute(k_sort, cudaFuncAttributeMaxDynamicSharedMemorySize,
                         32*CC*(int)sizeof(int));

    k_init<<<(BB*CC*DD + 255)/256, 256>>>(centersIn);
    k_t1<<<(BB*NN + 255)/256, 256>>>(data);
    for (int it = 0; it < ITERS; it++) {
        k_prep<<<(BB*CC + 255)/256, 256>>>();
        k_transpose<<<(BB*8*DD*64 + 255)/256, 256>>>();
        k_assign<<<dim3(NN/TILE_P, BB), 128, SMEM_BYTES>>>(data);
        k_sort<<<BB, 1024, 32*CC*(int)sizeof(int)>>>();
        k_update<<<dim3(CC, BB), 128>>>(data);
    }
    const size_t total = (size_t)BB*CC*DD + (size_t)BB*NN*DD;
    k_output<<<(unsigned)((total + 255)/256), 256>>>(out);
}

// round 10
// speedup vs baseline: 13.8208x; 1.1789x over previous
#include <cuda_runtime.h>
#include <cstdint>

#define BB 8
#define NN 65536
#define CC 512
#define DD 128
#define ITERS 10
#define TILE_P 64
#define QSTRIDE 516            // words per point-quad row (bank-staggered)
#define CROW 64                // words per k-row of non-dup 64-center chunk

// smem: points 16*516, two 32KB center buffers, cnorm 512  (~98 KB -> 2 CTA/SM)
#define SMEM_BYTES ((16*QSTRIDE + 2*128*CROW + CC) * 4)

__device__ float g_centers[BB*CC*DD];
__device__ float g_cT[BB*8*DD*64];      // [b][chunk64][k][c&63] k-major centers
__device__ float g_cnorm[BB*CC];
__device__ float g_t1[BB*NN];
__device__ int   g_assign[BB*NN];
__device__ int   g_list[BB*NN];
__device__ int   g_off[BB*CC];
__device__ int   g_cnt[BB*CC];

__device__ __forceinline__ void fma2(unsigned long long &d,
                                     unsigned long long a,
                                     unsigned long long b) {
    asm("fma.rn.f32x2 %0, %1, %2, %0;" : "+l"(d) : "l"(a), "l"(b));
}
__device__ __forceinline__ unsigned long long dup2(float x) {
    unsigned long long r;
    asm("mov.b64 %0, {%1, %1};" : "=l"(r) : "f"(x));
    return r;
}
__device__ __forceinline__ uint32_t smem_u32(const void* p) {
    uint32_t a;
    asm("{ .reg .u64 t; cvta.to.shared.u64 t, %1; cvt.u32.u64 %0, t; }"
        : "=r"(a) : "l"(p));
    return a;
}
__device__ __forceinline__ void cp16(uint32_t dsmem, const void* gsrc) {
    asm volatile("cp.async.cg.shared.global [%0], [%1], 16;"
                 :: "r"(dsmem), "l"(gsrc));
}
#define CP_COMMIT() asm volatile("cp.async.commit_group;" ::: "memory")
#define CP_WAIT0()  asm volatile("cp.async.wait_group 0;" ::: "memory")

// ---------------- exact-arithmetic building blocks (DO NOT REORDER) --------
// LLVM-style vectorized sum of v[k]^2: VF=4, IC=2, fma, lanewise, faddp.
__device__ __forceinline__ float norm128_llvm(const float* __restrict__ v) {
    float A0=0.f,A1=0.f,A2=0.f,A3=0.f;
    float B0=0.f,B1=0.f,B2=0.f,B3=0.f;
    #pragma unroll
    for (int i = 0; i < 16; i++) {
        const float* p = v + 8*i;
        A0 = __fmaf_rn(p[0], p[0], A0);
        A1 = __fmaf_rn(p[1], p[1], A1);
        A2 = __fmaf_rn(p[2], p[2], A2);
        A3 = __fmaf_rn(p[3], p[3], A3);
        B0 = __fmaf_rn(p[4], p[4], B0);
        B1 = __fmaf_rn(p[5], p[5], B1);
        B2 = __fmaf_rn(p[6], p[6], B2);
        B3 = __fmaf_rn(p[7], p[7], B3);
    }
    float S0 = __fadd_rn(A0, B0);
    float S1 = __fadd_rn(A1, B1);
    float S2 = __fadd_rn(A2, B2);
    float S3 = __fadd_rn(A3, B3);
    return __fadd_rn(__fadd_rn(S0, S1), __fadd_rn(S2, S3));
}

// ---------------------------------------------------------------------------
__global__ void k_init(const float* __restrict__ centersIn) {
    int i = blockIdx.x * blockDim.x + threadIdx.x;
    if (i < BB*CC*DD) g_centers[i] = centersIn[i];
}
__global__ void k_t1(const float* __restrict__ data) {
    int i = blockIdx.x * blockDim.x + threadIdx.x;
    if (i >= BB*NN) return;
    g_t1[i] = norm128_llvm(data + (size_t)i * DD);
}
__global__ void k_prep() {
    int i = blockIdx.x * blockDim.x + threadIdx.x;
    if (i >= BB*CC) return;
    g_cnorm[i] = norm128_llvm(g_centers + (size_t)i * DD);
}

// k-major chunked transpose: g_cT[b][c>>6][k][c&63] = g_centers[b][c][k]
__global__ void k_transpose() {
    int i = blockIdx.x * blockDim.x + threadIdx.x;
    if (i >= BB*CC*DD) return;
    int k = i & 127;
    int c = (i >> 7) & 511;
    int b = i >> 16;
    float v = g_centers[i];
    g_cT[(((size_t)(b*8 + (c >> 6))*DD + k) << 6) + (c & 63)] = v;
}

// ---------------------------------------------------------------------------
// Assign: exact fp32 fma2 chains, all 512 centers, cp.async double-buffered.
// grid = (N/64, B), block = 128, 2 CTAs/SM. Thread: 8 points x 4 centers.
__global__ void __launch_bounds__(128, 2) k_assign(const float* __restrict__ data) {
    extern __shared__ float sm[];
    float* ptsS  = sm;                      // [16 quads][QSTRIDE]
    float* cenB0 = ptsS + 16*QSTRIDE;       // buffer 0: [128 k][CROW]
    float* cenB1 = cenB0 + 128*CROW;        // buffer 1
    float* cnS   = cenB1 + 128*CROW;        // [512]

    const int b  = blockIdx.y;
    const int n0 = blockIdx.x * TILE_P;
    const int tid = threadIdx.x;
    const int pg = tid >> 4;   // 0..7 : points 8pg..8pg+7 (quads 2pg,2pg+1)
    const int cg = tid & 15;   // 0..15: centers 4cg..4cg+3 within chunk

    for (int i = tid; i < CC; i += 128) cnS[i] = g_cnorm[b*CC + i];

    // point tile, quad-packed: ptsS[p>>2][4k + (p&3)] = x_p[k]
    const float* dptr = data + ((size_t)b*NN + n0) * DD;
    for (int idx = tid; idx < TILE_P*32; idx += 128) {
        int p = idx >> 5;
        int q = idx & 31;
        float4 v = __ldg((const float4*)(dptr + (size_t)p*DD) + q);
        float* dst = ptsS + (p >> 2)*QSTRIDE + (p & 3);
        int k4 = q * 4;
        dst[(k4+0)*4] = v.x; dst[(k4+1)*4] = v.y;
        dst[(k4+2)*4] = v.z; dst[(k4+3)*4] = v.w;
    }

    float t1r[8];
    #pragma unroll
    for (int i = 0; i < 8; i++) t1r[i] = g_t1[b*NN + n0 + 8*pg + i];

    float bv[8]; int bi[8];
    #pragma unroll
    for (int i = 0; i < 8; i++) { bv[i] = 3.4e38f; bi[i] = 0; }

    const char* csrc = (const char*)(g_cT + (size_t)b*8*DD*64);
    const uint32_t sb0 = smem_u32(cenB0);
    const uint32_t sb1 = smem_u32(cenB1);

    // prefetch chunk 0 into buffer 0 (32KB = 2048 x 16B, 16 per thread)
    #pragma unroll
    for (int j = 0; j < 16; j++)
        cp16(sb0 + j*2048 + tid*16, csrc + j*2048 + tid*16);
    CP_COMMIT();

    const float* q0p = ptsS + (2*pg)*QSTRIDE;
    const float* q1p = q0p + QSTRIDE;

    for (int ch = 0; ch < 8; ch++) {
        CP_WAIT0();
        __syncthreads();   // chunk ch arrived; prior compute done

        if (ch < 7) {      // prefetch ch+1 into the other buffer
            uint32_t nb = ((ch + 1) & 1) ? sb1 : sb0;
            const char* src = csrc + (size_t)(ch + 1)*DD*64*4;
            #pragma unroll
            for (int j = 0; j < 16; j++)
                cp16(nb + j*2048 + tid*16, src + j*2048 + tid*16);
            CP_COMMIT();
        }

        const float* cw = ((ch & 1) ? cenB1 : cenB0) + 4*cg;

        unsigned long long acc[4][4];   // [point pair][center j]
        #pragma unroll
        for (int q = 0; q < 4; q++)
            #pragma unroll
            for (int j = 0; j < 4; j++) acc[q][j] = 0ull;

        #pragma unroll 4
        for (int k = 0; k < DD; k++) {
            ulonglong2 Q0 = *(const ulonglong2*)(q0p + 4*k);  // pts 8pg..+3
            ulonglong2 Q1 = *(const ulonglong2*)(q1p + 4*k);  // pts 8pg+4..+7
            float4 C4 = *(const float4*)(cw + k*CROW);
            unsigned long long c0d = dup2(C4.x), c1d = dup2(C4.y);
            unsigned long long c2d = dup2(C4.z), c3d = dup2(C4.w);
            fma2(acc[0][0], Q0.x, c0d); fma2(acc[1][0], Q0.y, c0d);
            fma2(acc[2][0], Q1.x, c0d); fma2(acc[3][0], Q1.y, c0d);
            fma2(acc[0][1], Q0.x, c1d); fma2(acc[1][1], Q0.y, c1d);
            fma2(acc[2][1], Q1.x, c1d); fma2(acc[3][1], Q1.y, c1d);
            fma2(acc[0][2], Q0.x, c2d); fma2(acc[1][2], Q0.y, c2d);
            fma2(acc[2][2], Q1.x, c2d); fma2(acc[3][2], Q1.y, c2d);
            fma2(acc[0][3], Q0.x, c3d); fma2(acc[1][3], Q0.y, c3d);
            fma2(acc[2][3], Q1.x, c3d); fma2(acc[3][3], Q1.y, c3d);
        }

        // epilogue: s = (t1 - 2*dot) + cn, rn ops in reference association
        int c0 = ch * 64 + 4*cg;
        #pragma unroll
        for (int j = 0; j < 4; j++) {
            int cidx = c0 + j;
            float cn = cnS[cidx];
            #pragma unroll
            for (int q = 0; q < 4; q++) {
                float2 f = *(float2*)&acc[q][j];
                float slo = __fadd_rn(__fsub_rn(t1r[2*q],
                                      __fmul_rn(2.0f, f.x)), cn);
                float shi = __fadd_rn(__fsub_rn(t1r[2*q+1],
                                      __fmul_rn(2.0f, f.y)), cn);
                if (slo < bv[2*q])   { bv[2*q]   = slo; bi[2*q]   = cidx; }
                if (shi < bv[2*q+1]) { bv[2*q+1] = shi; bi[2*q+1] = cidx; }
            }
        }
    }

    // argmin across the 16 cg-lanes per point (tie -> lowest index)
    #pragma unroll
    for (int i = 0; i < 8; i++) {
        float v = bv[i]; int ix = bi[i];
        #pragma unroll
        for (int off = 1; off <= 8; off <<= 1) {
            float ov = __shfl_xor_sync(0xffffffffu, v, off);
            int   oi = __shfl_xor_sync(0xffffffffu, ix, off);
            if (ov < v || (ov == v && oi < ix)) { v = ov; ix = oi; }
        }
        if (cg == 0) g_assign[b*NN + n0 + 8*pg + i] = ix;
    }
}

// ---------------------------------------------------------------------------
// Stable counting sort of points by cluster (ascending n within cluster).
__global__ void k_sort() {
    __shared__ int hist[CC];
    __shared__ int cursor[CC];
    __shared__ int wt[CC];
    extern __shared__ int W[];   // [32 warps][CC]

    int b = blockIdx.x, tid = threadIdx.x;
    int w = tid >> 5, lane = tid & 31;

    for (int i = tid; i < CC; i += 1024) hist[i] = 0;
    __syncthreads();
    for (int n = tid; n < NN; n += 1024)
        atomicAdd(&hist[g_assign[b*NN + n]], 1);
    __syncthreads();
    if (tid == 0) {
        int run = 0;
        for (int c = 0; c < CC; c++) {
            cursor[c] = run;
            g_off[b*CC + c] = run;
            int h = hist[c];
            g_cnt[b*CC + c] = h;
            run += h;
        }
    }
    __syncthreads();

    for (int wave = 0; wave < NN/1024; wave++) {
        for (int i = tid; i < 32*CC; i += 1024) W[i] = 0;
        __syncthreads();
        int n = wave*1024 + tid;
        int a = g_assign[b*NN + n];
        unsigned mask = __match_any_sync(0xffffffffu, a);
        int rank = __popc(mask & ((1u << lane) - 1u));
        if (rank == 0) W[w*CC + a] = __popc(mask);
        __syncthreads();
        if (tid < CC) {
            int s = 0;
            for (int ww = 0; ww < 32; ww++) {
                int t = W[ww*CC + tid];
                W[ww*CC + tid] = s;
                s += t;
            }
            wt[tid] = s;
        }
        __syncthreads();
        int pos = cursor[a] + W[w*CC + a] + rank;
        g_list[b*NN + pos] = n;
        __syncthreads();
        if (tid < CC) cursor[tid] += wt[tid];
        __syncthreads();
    }
}

// ---------------------------------------------------------------------------
// New centers: sequential ascending-n fp32 adds per (b,c,d), then rn divide.
// Unrolled x8: loads batched (independent), adds strictly in ascending order.
__global__ void k_update(const float* __restrict__ data) {
    __shared__ int listS[128];
    int c = blockIdx.x, b = blockIdx.y, d = threadIdx.x;
    int off = g_off[b*CC + c];
    int cnt = g_cnt[b*CC + c];
    const float* db = data + (size_t)b*NN*DD + d;
    float acc = 0.f;
    for (int base = 0; base < cnt; base += 128) {
        __syncthreads();
        int m = min(128, cnt - base);
        if (d < m) listS[d] = g_list[b*NN + off + base + d];
        __syncthreads();
        int j = 0;
        for (; j + 8 <= m; j += 8) {
            float v0 = __ldg(db + (size_t)listS[j+0]*DD);
            float v1 = __ldg(db + (size_t)listS[j+1]*DD);
            float v2 = __ldg(db + (size_t)listS[j+2]*DD);
            float v3 = __ldg(db + (size_t)listS[j+3]*DD);
            float v4 = __ldg(db + (size_t)listS[j+4]*DD);
            float v5 = __ldg(db + (size_t)listS[j+5]*DD);
            float v6 = __ldg(db + (size_t)listS[j+6]*DD);
            float v7 = __ldg(db + (size_t)listS[j+7]*DD);
            acc = __fadd_rn(acc, v0); acc = __fadd_rn(acc, v1);
            acc = __fadd_rn(acc, v2); acc = __fadd_rn(acc, v3);
            acc = __fadd_rn(acc, v4); acc = __fadd_rn(acc, v5);
            acc = __fadd_rn(acc, v6); acc = __fadd_rn(acc, v7);
        }
        for (; j < m; j++)
            acc = __fadd_rn(acc, __ldg(db + (size_t)listS[j]*DD));
    }
    if (cnt > 0)
        g_centers[(size_t)(b*CC + c)*DD + d] = __fdiv_rn(acc, __int2float_rn(cnt));
}

// d_out = [centers (B*C*D) | (float)assign broadcast over D (B*N*D)]
__global__ void k_output(float* __restrict__ out) {
    size_t i = (size_t)blockIdx.x * blockDim.x + threadIdx.x;
    const size_t nc = (size_t)BB*CC*DD;
    const size_t total = nc + (size_t)BB*NN*DD;
    if (i >= total) return;
    if (i < nc) out[i] = g_centers[i];
    else {
        size_t j = i - nc;
        out[i] = (float)g_assign[j >> 7];
    }
}

// ---------------------------------------------------------------------------
extern "C" void kernel_launch(void* const* d_in, const int* in_sizes, int n_in,
                              void* d_out, int out_size) {
    const float* data      = (const float*)d_in[0];
    const float* centersIn = (const float*)d_in[1];
    float* out = (float*)d_out;

    cudaFuncSetAttribute(k_assign, cudaFuncAttributeMaxDynamicSharedMemorySize,
                         SMEM_BYTES);
    cudaFuncSetAttribute(k_sort, cudaFuncAttributeMaxDynamicSharedMemorySize,
                         32*CC*(int)sizeof(int));

    k_init<<<(BB*CC*DD + 255)/256, 256>>>(centersIn);
    k_t1<<<(BB*NN + 255)/256, 256>>>(data);
    for (int it = 0; it < ITERS; it++) {
        k_prep<<<(BB*CC + 63)/64, 64>>>();
        k_transpose<<<(BB*CC*DD + 255)/256, 256>>>();
        k_assign<<<dim3(NN/TILE_P, BB), 128, SMEM_BYTES>>>(data);
        k_sort<<<BB, 1024, 32*CC*(int)sizeof(int)>>>();
        k_update<<<dim3(CC, BB), 128>>>(data);
    }
    const size_t total = (size_t)BB*CC*DD + (size_t)BB*NN*DD;
    k_output<<<(unsigned)((total + 255)/256), 256>>>(out);
}

// round 11
// speedup vs baseline: 14.6728x; 1.0616x over previous
#include <cuda_runtime.h>
#include <cstdint>

#define BB 8
#define NN 65536
#define CC 512
#define DD 128
#define ITERS 10
#define TILE_P 64
#define QSTRIDE 516            // words per point-quad row (bank-staggered)
#define CROW 64                // words per k-row of non-dup 64-center chunk

// smem: points 16*516, ONE 32KB center buffer, cnorm 512 (~66 KB -> 3 CTA/SM)
#define SMEM_BYTES ((16*QSTRIDE + 128*CROW + CC) * 4)

__device__ float g_centers[BB*CC*DD];
__device__ float g_cT[BB*8*DD*64];      // [b][chunk64][k][c&63] k-major centers
__device__ float g_cnorm[BB*CC];
__device__ float g_t1[BB*NN];
__device__ int   g_assign[BB*NN];
__device__ int   g_list[BB*NN];
__device__ int   g_off[BB*CC];
__device__ int   g_cnt[BB*CC];

__device__ __forceinline__ void fma2(unsigned long long &d,
                                     unsigned long long a,
                                     unsigned long long b) {
    asm("fma.rn.f32x2 %0, %1, %2, %0;" : "+l"(d) : "l"(a), "l"(b));
}
__device__ __forceinline__ unsigned long long dup2(float x) {
    unsigned long long r;
    asm("mov.b64 %0, {%1, %1};" : "=l"(r) : "f"(x));
    return r;
}
__device__ __forceinline__ uint32_t smem_u32(const void* p) {
    uint32_t a;
    asm("{ .reg .u64 t; cvta.to.shared.u64 t, %1; cvt.u32.u64 %0, t; }"
        : "=r"(a) : "l"(p));
    return a;
}
__device__ __forceinline__ void cp16(uint32_t dsmem, const void* gsrc) {
    asm volatile("cp.async.cg.shared.global [%0], [%1], 16;"
                 :: "r"(dsmem), "l"(gsrc));
}
#define CP_COMMIT() asm volatile("cp.async.commit_group;" ::: "memory")
#define CP_WAIT0()  asm volatile("cp.async.wait_group 0;" ::: "memory")

// ---------------- exact-arithmetic building blocks (DO NOT REORDER) --------
// LLVM-style vectorized sum of v[k]^2: VF=4, IC=2, fma, lanewise, faddp.
__device__ __forceinline__ float norm128_llvm(const float* __restrict__ v) {
    float A0=0.f,A1=0.f,A2=0.f,A3=0.f;
    float B0=0.f,B1=0.f,B2=0.f,B3=0.f;
    #pragma unroll
    for (int i = 0; i < 16; i++) {
        const float* p = v + 8*i;
        A0 = __fmaf_rn(p[0], p[0], A0);
        A1 = __fmaf_rn(p[1], p[1], A1);
        A2 = __fmaf_rn(p[2], p[2], A2);
        A3 = __fmaf_rn(p[3], p[3], A3);
        B0 = __fmaf_rn(p[4], p[4], B0);
        B1 = __fmaf_rn(p[5], p[5], B1);
        B2 = __fmaf_rn(p[6], p[6], B2);
        B3 = __fmaf_rn(p[7], p[7], B3);
    }
    float S0 = __fadd_rn(A0, B0);
    float S1 = __fadd_rn(A1, B1);
    float S2 = __fadd_rn(A2, B2);
    float S3 = __fadd_rn(A3, B3);
    return __fadd_rn(__fadd_rn(S0, S1), __fadd_rn(S2, S3));
}

// ---------------------------------------------------------------------------
__global__ void k_init(const float* __restrict__ centersIn) {
    int i = blockIdx.x * blockDim.x + threadIdx.x;
    if (i < BB*CC*DD) g_centers[i] = centersIn[i];
}
__global__ void k_t1(const float* __restrict__ data) {
    int i = blockIdx.x * blockDim.x + threadIdx.x;
    if (i >= BB*NN) return;
    g_t1[i] = norm128_llvm(data + (size_t)i * DD);
}
__global__ void k_prep() {
    int i = blockIdx.x * blockDim.x + threadIdx.x;
    if (i >= BB*CC) return;
    g_cnorm[i] = norm128_llvm(g_centers + (size_t)i * DD);
}

// k-major chunked transpose: g_cT[b][c>>6][k][c&63] = g_centers[b][c][k]
__global__ void k_transpose() {
    int i = blockIdx.x * blockDim.x + threadIdx.x;
    if (i >= BB*CC*DD) return;
    int k = i & 127;
    int c = (i >> 7) & 511;
    int b = i >> 16;
    float v = g_centers[i];
    g_cT[(((size_t)(b*8 + (c >> 6))*DD + k) << 6) + (c & 63)] = v;
}

// ---------------------------------------------------------------------------
// Assign: exact fp32 fma2 chains, all 512 centers, single-buffered chunks,
// latency hidden by 3 CTAs/SM. grid=(N/64,B), block=128, 8 pts x 4 centers.
__global__ void __launch_bounds__(128, 3) k_assign(const float* __restrict__ data) {
    extern __shared__ float sm[];
    float* ptsS = sm;                       // [16 quads][QSTRIDE]
    float* cenB = ptsS + 16*QSTRIDE;        // [128 k][CROW]
    float* cnS  = cenB + 128*CROW;          // [512]

    const int b  = blockIdx.y;
    const int n0 = blockIdx.x * TILE_P;
    const int tid = threadIdx.x;
    const int pg = tid >> 4;   // 0..7 : points 8pg..8pg+7 (quads 2pg,2pg+1)
    const int cg = tid & 15;   // 0..15: centers 4cg..4cg+3 within chunk

    for (int i = tid; i < CC; i += 128) cnS[i] = g_cnorm[b*CC + i];

    // point tile, quad-packed: ptsS[p>>2][4k + (p&3)] = x_p[k]
    const float* dptr = data + ((size_t)b*NN + n0) * DD;
    for (int idx = tid; idx < TILE_P*32; idx += 128) {
        int p = idx >> 5;
        int q = idx & 31;
        float4 v = __ldg((const float4*)(dptr + (size_t)p*DD) + q);
        float* dst = ptsS + (p >> 2)*QSTRIDE + (p & 3);
        int k4 = q * 4;
        dst[(k4+0)*4] = v.x; dst[(k4+1)*4] = v.y;
        dst[(k4+2)*4] = v.z; dst[(k4+3)*4] = v.w;
    }

    float t1r[8];
    #pragma unroll
    for (int i = 0; i < 8; i++) t1r[i] = g_t1[b*NN + n0 + 8*pg + i];

    float bv[8]; int bi[8];
    #pragma unroll
    for (int i = 0; i < 8; i++) { bv[i] = 3.4e38f; bi[i] = 0; }

    const char* csrc = (const char*)(g_cT + (size_t)b*8*DD*64);
    const uint32_t sbc = smem_u32(cenB);

    const float* q0p = ptsS + (2*pg)*QSTRIDE;
    const float* q1p = q0p + QSTRIDE;
    const float* cw = cenB + 4*cg;

    for (int ch = 0; ch < 8; ch++) {
        __syncthreads();   // prior chunk's compute done before overwrite
        // load chunk ch (32KB = 2048 x 16B, 16 per thread)
        const char* src = csrc + (size_t)ch*DD*64*4;
        #pragma unroll
        for (int j = 0; j < 16; j++)
            cp16(sbc + j*2048 + tid*16, src + j*2048 + tid*16);
        CP_COMMIT();
        CP_WAIT0();
        __syncthreads();   // chunk visible to all warps

        unsigned long long acc[4][4];   // [point pair][center j]
        #pragma unroll
        for (int q = 0; q < 4; q++)
            #pragma unroll
            for (int j = 0; j < 4; j++) acc[q][j] = 0ull;

        #pragma unroll 4
        for (int k = 0; k < DD; k++) {
            ulonglong2 Q0 = *(const ulonglong2*)(q0p + 4*k);  // pts 8pg..+3
            ulonglong2 Q1 = *(const ulonglong2*)(q1p + 4*k);  // pts 8pg+4..+7
            float4 C4 = *(const float4*)(cw + k*CROW);
            unsigned long long c0d = dup2(C4.x), c1d = dup2(C4.y);
            unsigned long long c2d = dup2(C4.z), c3d = dup2(C4.w);
            fma2(acc[0][0], Q0.x, c0d); fma2(acc[1][0], Q0.y, c0d);
            fma2(acc[2][0], Q1.x, c0d); fma2(acc[3][0], Q1.y, c0d);
            fma2(acc[0][1], Q0.x, c1d); fma2(acc[1][1], Q0.y, c1d);
            fma2(acc[2][1], Q1.x, c1d); fma2(acc[3][1], Q1.y, c1d);
            fma2(acc[0][2], Q0.x, c2d); fma2(acc[1][2], Q0.y, c2d);
            fma2(acc[2][2], Q1.x, c2d); fma2(acc[3][2], Q1.y, c2d);
            fma2(acc[0][3], Q0.x, c3d); fma2(acc[1][3], Q0.y, c3d);
            fma2(acc[2][3], Q1.x, c3d); fma2(acc[3][3], Q1.y, c3d);
        }

        // epilogue: s = (t1 - 2*dot) + cn, rn ops in reference association
        int c0 = ch * 64 + 4*cg;
        #pragma unroll
        for (int j = 0; j < 4; j++) {
            int cidx = c0 + j;
            float cn = cnS[cidx];
            #pragma unroll
            for (int q = 0; q < 4; q++) {
                float2 f = *(float2*)&acc[q][j];
                float slo = __fadd_rn(__fsub_rn(t1r[2*q],
                                      __fmul_rn(2.0f, f.x)), cn);
                float shi = __fadd_rn(__fsub_rn(t1r[2*q+1],
                                      __fmul_rn(2.0f, f.y)), cn);
                if (slo < bv[2*q])   { bv[2*q]   = slo; bi[2*q]   = cidx; }
                if (shi < bv[2*q+1]) { bv[2*q+1] = shi; bi[2*q+1] = cidx; }
            }
        }
    }

    // argmin across the 16 cg-lanes per point (tie -> lowest index)
    #pragma unroll
    for (int i = 0; i < 8; i++) {
        float v = bv[i]; int ix = bi[i];
        #pragma unroll
        for (int off = 1; off <= 8; off <<= 1) {
            float ov = __shfl_xor_sync(0xffffffffu, v, off);
            int   oi = __shfl_xor_sync(0xffffffffu, ix, off);
            if (ov < v || (ov == v && oi < ix)) { v = ov; ix = oi; }
        }
        if (cg == 0) g_assign[b*NN + n0 + 8*pg + i] = ix;
    }
}

// ---------------------------------------------------------------------------
// Stable counting sort of points by cluster (ascending n within cluster).
__global__ void k_sort() {
    __shared__ int hist[CC];
    __shared__ int cursor[CC];
    __shared__ int wt[CC];
    extern __shared__ int W[];   // [32 warps][CC]

    int b = blockIdx.x, tid = threadIdx.x;
    int w = tid >> 5, lane = tid & 31;

    for (int i = tid; i < CC; i += 1024) hist[i] = 0;
    __syncthreads();
    for (int n = tid; n < NN; n += 1024)
        atomicAdd(&hist[g_assign[b*NN + n]], 1);
    __syncthreads();
    if (tid == 0) {
        int run = 0;
        for (int c = 0; c < CC; c++) {
            cursor[c] = run;
            g_off[b*CC + c] = run;
            int h = hist[c];
            g_cnt[b*CC + c] = h;
            run += h;
        }
    }
    __syncthreads();

    for (int wave = 0; wave < NN/1024; wave++) {
        for (int i = tid; i < 32*CC; i += 1024) W[i] = 0;
        __syncthreads();
        int n = wave*1024 + tid;
        int a = g_assign[b*NN + n];
        unsigned mask = __match_any_sync(0xffffffffu, a);
        int rank = __popc(mask & ((1u << lane) - 1u));
        if (rank == 0) W[w*CC + a] = __popc(mask);
        __syncthreads();
        if (tid < CC) {
            int s = 0;
            for (int ww = 0; ww < 32; ww++) {
                int t = W[ww*CC + tid];
                W[ww*CC + tid] = s;
                s += t;
            }
            wt[tid] = s;
        }
        __syncthreads();
        int pos = cursor[a] + W[w*CC + a] + rank;
        g_list[b*NN + pos] = n;
        __syncthreads();
        if (tid < CC) cursor[tid] += wt[tid];
        __syncthreads();
    }
}

// ---------------------------------------------------------------------------
// New centers: sequential ascending-n fp32 adds per (b,c,d), then rn divide.
// Unrolled x8: loads batched (independent), adds strictly in ascending order.
__global__ void k_update(const float* __restrict__ data) {
    __shared__ int listS[128];
    int c = blockIdx.x, b = blockIdx.y, d = threadIdx.x;
    int off = g_off[b*CC + c];
    int cnt = g_cnt[b*CC + c];
    const float* db = data + (size_t)b*NN*DD + d;
    float acc = 0.f;
    for (int base = 0; base < cnt; base += 128) {
        __syncthreads();
        int m = min(128, cnt - base);
        if (d < m) listS[d] = g_list[b*NN + off + base + d];
        __syncthreads();
        int j = 0;
        for (; j + 8 <= m; j += 8) {
            float v0 = __ldg(db + (size_t)listS[j+0]*DD);
            float v1 = __ldg(db + (size_t)listS[j+1]*DD);
            float v2 = __ldg(db + (size_t)listS[j+2]*DD);
            float v3 = __ldg(db + (size_t)listS[j+3]*DD);
            float v4 = __ldg(db + (size_t)listS[j+4]*DD);
            float v5 = __ldg(db + (size_t)listS[j+5]*DD);
            float v6 = __ldg(db + (size_t)listS[j+6]*DD);
            float v7 = __ldg(db + (size_t)listS[j+7]*DD);
            acc = __fadd_rn(acc, v0); acc = __fadd_rn(acc, v1);
            acc = __fadd_rn(acc, v2); acc = __fadd_rn(acc, v3);
            acc = __fadd_rn(acc, v4); acc = __fadd_rn(acc, v5);
            acc = __fadd_rn(acc, v6); acc = __fadd_rn(acc, v7);
        }
        for (; j < m; j++)
            acc = __fadd_rn(acc, __ldg(db + (size_t)listS[j]*DD));
    }
    if (cnt > 0)
        g_centers[(size_t)(b*CC + c)*DD + d] = __fdiv_rn(acc, __int2float_rn(cnt));
}

// d_out = [centers (B*C*D) | (float)assign broadcast over D (B*N*D)]
__global__ void k_output(float* __restrict__ out) {
    size_t i = (size_t)blockIdx.x * blockDim.x + threadIdx.x;
    const size_t nc = (size_t)BB*CC*DD;
    const size_t total = nc + (size_t)BB*NN*DD;
    if (i >= total) return;
    if (i < nc) out[i] = g_centers[i];
    else {
        size_t j = i - nc;
        out[i] = (float)g_assign[j >> 7];
    }
}

// ---------------------------------------------------------------------------
extern "C" void kernel_launch(void* const* d_in, const int* in_sizes, int n_in,
                              void* d_out, int out_size) {
    const float* data      = (const float*)d_in[0];
    const float* centersIn = (const float*)d_in[1];
    float* out = (float*)d_out;

    cudaFuncSetAttribute(k_assign, cudaFuncAttributeMaxDynamicSharedMemorySize,
                         SMEM_BYTES);
    cudaFuncSetAttribute(k_sort, cudaFuncAttributeMaxDynamicSharedMemorySize,
                         32*CC*(int)sizeof(int));

    k_init<<<(BB*CC*DD + 255)/256, 256>>>(centersIn);
    k_t1<<<(BB*NN + 255)/256, 256>>>(data);
    for (int it = 0; it < ITERS; it++) {
        k_prep<<<(BB*CC + 63)/64, 64>>>();
        k_transpose<<<(BB*CC*DD + 255)/256, 256>>>();
        k_assign<<<dim3(NN/TILE_P, BB), 128, SMEM_BYTES>>>(data);
        k_sort<<<BB, 1024, 32*CC*(int)sizeof(int)>>>();
        k_update<<<dim3(CC, BB), 128>>>(data);
    }
    const size_t total = (size_t)BB*CC*DD + (size_t)BB*NN*DD;
    k_output<<<(unsigned)((total + 255)/256), 256>>>(out);
}

// round 12
// speedup vs baseline: 14.8064x; 1.0091x over previous
#include <cuda_runtime.h>
#include <cstdint>

#define BB 8
#define NN 65536
#define CC 512
#define DD 128
#define ITERS 10
#define TILE_P 128
#define QSTRIDE 516            // words per point-quad row (bank-staggered)
#define CROW 64                // words per k-row of non-dup 64-center chunk

// smem: points 32*516, ONE 32KB center buffer, cnorm 512 (~98.5KB -> 2 CTA/SM)
#define SMEM_BYTES ((32*QSTRIDE + 128*CROW + CC) * 4)

__device__ float g_centers[BB*CC*DD];
__device__ float g_cT[BB*8*DD*64];      // [b][chunk64][k][c&63] k-major centers
__device__ float g_cnorm[BB*CC];
__device__ float g_t1[BB*NN];
__device__ int   g_assign[BB*NN];
__device__ int   g_list[BB*NN];
__device__ int   g_off[BB*CC];
__device__ int   g_cnt[BB*CC];

__device__ __forceinline__ void fma2(unsigned long long &d,
                                     unsigned long long a,
                                     unsigned long long b) {
    asm("fma.rn.f32x2 %0, %1, %2, %0;" : "+l"(d) : "l"(a), "l"(b));
}
__device__ __forceinline__ unsigned long long dup2(float x) {
    unsigned long long r;
    asm("mov.b64 %0, {%1, %1};" : "=l"(r) : "f"(x));
    return r;
}
__device__ __forceinline__ uint32_t smem_u32(const void* p) {
    uint32_t a;
    asm("{ .reg .u64 t; cvta.to.shared.u64 t, %1; cvt.u32.u64 %0, t; }"
        : "=r"(a) : "l"(p));
    return a;
}
__device__ __forceinline__ void cp16(uint32_t dsmem, const void* gsrc) {
    asm volatile("cp.async.cg.shared.global [%0], [%1], 16;"
                 :: "r"(dsmem), "l"(gsrc));
}
#define CP_COMMIT() asm volatile("cp.async.commit_group;" ::: "memory")
#define CP_WAIT0()  asm volatile("cp.async.wait_group 0;" ::: "memory")

// ---------------- exact-arithmetic building blocks (DO NOT REORDER) --------
// LLVM-style vectorized sum of v[k]^2: VF=4, IC=2, fma, lanewise, faddp.
__device__ __forceinline__ float norm128_llvm(const float* __restrict__ v) {
    float A0=0.f,A1=0.f,A2=0.f,A3=0.f;
    float B0=0.f,B1=0.f,B2=0.f,B3=0.f;
    #pragma unroll
    for (int i = 0; i < 16; i++) {
        const float* p = v + 8*i;
        A0 = __fmaf_rn(p[0], p[0], A0);
        A1 = __fmaf_rn(p[1], p[1], A1);
        A2 = __fmaf_rn(p[2], p[2], A2);
        A3 = __fmaf_rn(p[3], p[3], A3);
        B0 = __fmaf_rn(p[4], p[4], B0);
        B1 = __fmaf_rn(p[5], p[5], B1);
        B2 = __fmaf_rn(p[6], p[6], B2);
        B3 = __fmaf_rn(p[7], p[7], B3);
    }
    float S0 = __fadd_rn(A0, B0);
    float S1 = __fadd_rn(A1, B1);
    float S2 = __fadd_rn(A2, B2);
    float S3 = __fadd_rn(A3, B3);
    return __fadd_rn(__fadd_rn(S0, S1), __fadd_rn(S2, S3));
}

// ---------------------------------------------------------------------------
__global__ void k_init(const float* __restrict__ centersIn) {
    int i = blockIdx.x * blockDim.x + threadIdx.x;
    if (i < BB*CC*DD) g_centers[i] = centersIn[i];
}
__global__ void k_t1(const float* __restrict__ data) {
    int i = blockIdx.x * blockDim.x + threadIdx.x;
    if (i >= BB*NN) return;
    g_t1[i] = norm128_llvm(data + (size_t)i * DD);
}
__global__ void k_prep() {
    int i = blockIdx.x * blockDim.x + threadIdx.x;
    if (i >= BB*CC) return;
    g_cnorm[i] = norm128_llvm(g_centers + (size_t)i * DD);
}

// k-major chunked transpose: g_cT[b][c>>6][k][c&63] = g_centers[b][c][k]
__global__ void k_transpose() {
    int i = blockIdx.x * blockDim.x + threadIdx.x;
    if (i >= BB*CC*DD) return;
    int k = i & 127;
    int c = (i >> 7) & 511;
    int b = i >> 16;
    float v = g_centers[i];
    g_cT[(((size_t)(b*8 + (c >> 6))*DD + k) << 6) + (c & 63)] = v;
}

// ---------------------------------------------------------------------------
// Assign: exact fp32 fma2 chains, all 512 centers, single-buffered chunks,
// 2 CTA/SM x 8 warps = 4 warps/SMSP. grid=(N/128,B), block=256,
// per thread: 8 points x 4 centers.
__global__ void __launch_bounds__(256, 2) k_assign(const float* __restrict__ data) {
    extern __shared__ float sm[];
    float* ptsS = sm;                       // [32 quads][QSTRIDE]
    float* cenB = ptsS + 32*QSTRIDE;        // [128 k][CROW]
    float* cnS  = cenB + 128*CROW;          // [512]

    const int b  = blockIdx.y;
    const int n0 = blockIdx.x * TILE_P;
    const int tid = threadIdx.x;
    const int pg = tid >> 4;   // 0..15: points 8pg..8pg+7 (quads 2pg,2pg+1)
    const int cg = tid & 15;   // 0..15: centers 4cg..4cg+3 within chunk

    for (int i = tid; i < CC; i += 256) cnS[i] = g_cnorm[b*CC + i];

    // point tile, quad-packed: ptsS[p>>2][4k + (p&3)] = x_p[k]
    const float* dptr = data + ((size_t)b*NN + n0) * DD;
    for (int idx = tid; idx < TILE_P*32; idx += 256) {
        int p = idx >> 5;
        int q = idx & 31;
        float4 v = __ldg((const float4*)(dptr + (size_t)p*DD) + q);
        float* dst = ptsS + (p >> 2)*QSTRIDE + (p & 3);
        int k4 = q * 4;
        dst[(k4+0)*4] = v.x; dst[(k4+1)*4] = v.y;
        dst[(k4+2)*4] = v.z; dst[(k4+3)*4] = v.w;
    }

    float t1r[8];
    #pragma unroll
    for (int i = 0; i < 8; i++) t1r[i] = g_t1[b*NN + n0 + 8*pg + i];

    float bv[8]; int bi[8];
    #pragma unroll
    for (int i = 0; i < 8; i++) { bv[i] = 3.4e38f; bi[i] = 0; }

    const char* csrc = (const char*)(g_cT + (size_t)b*8*DD*64);
    const uint32_t sbc = smem_u32(cenB);

    const float* q0p = ptsS + (2*pg)*QSTRIDE;
    const float* q1p = q0p + QSTRIDE;
    const float* cw = cenB + 4*cg;

    for (int ch = 0; ch < 8; ch++) {
        __syncthreads();   // prior chunk's compute done before overwrite
        // load chunk ch (32KB = 2048 x 16B, 8 per thread)
        const char* src = csrc + (size_t)ch*DD*64*4;
        #pragma unroll
        for (int j = 0; j < 8; j++)
            cp16(sbc + j*4096 + tid*16, src + j*4096 + tid*16);
        CP_COMMIT();
        CP_WAIT0();
        __syncthreads();   // chunk visible to all warps

        unsigned long long acc[4][4];   // [point pair][center j]
        #pragma unroll
        for (int q = 0; q < 4; q++)
            #pragma unroll
            for (int j = 0; j < 4; j++) acc[q][j] = 0ull;

        #pragma unroll 4
        for (int k = 0; k < DD; k++) {
            ulonglong2 Q0 = *(const ulonglong2*)(q0p + 4*k);  // pts 8pg..+3
            ulonglong2 Q1 = *(const ulonglong2*)(q1p + 4*k);  // pts 8pg+4..+7
            float4 C4 = *(const float4*)(cw + k*CROW);
            unsigned long long c0d = dup2(C4.x), c1d = dup2(C4.y);
            unsigned long long c2d = dup2(C4.z), c3d = dup2(C4.w);
            fma2(acc[0][0], Q0.x, c0d); fma2(acc[1][0], Q0.y, c0d);
            fma2(acc[2][0], Q1.x, c0d); fma2(acc[3][0], Q1.y, c0d);
            fma2(acc[0][1], Q0.x, c1d); fma2(acc[1][1], Q0.y, c1d);
            fma2(acc[2][1], Q1.x, c1d); fma2(acc[3][1], Q1.y, c1d);
            fma2(acc[0][2], Q0.x, c2d); fma2(acc[1][2], Q0.y, c2d);
            fma2(acc[2][2], Q1.x, c2d); fma2(acc[3][2], Q1.y, c2d);
            fma2(acc[0][3], Q0.x, c3d); fma2(acc[1][3], Q0.y, c3d);
            fma2(acc[2][3], Q1.x, c3d); fma2(acc[3][3], Q1.y, c3d);
        }

        // epilogue: s = (t1 - 2*dot) + cn, rn ops in reference association
        int c0 = ch * 64 + 4*cg;
        #pragma unroll
        for (int j = 0; j < 4; j++) {
            int cidx = c0 + j;
            float cn = cnS[cidx];
            #pragma unroll
            for (int q = 0; q < 4; q++) {
                float2 f = *(float2*)&acc[q][j];
                float slo = __fadd_rn(__fsub_rn(t1r[2*q],
                                      __fmul_rn(2.0f, f.x)), cn);
                float shi = __fadd_rn(__fsub_rn(t1r[2*q+1],
                                      __fmul_rn(2.0f, f.y)), cn);
                if (slo < bv[2*q])   { bv[2*q]   = slo; bi[2*q]   = cidx; }
                if (shi < bv[2*q+1]) { bv[2*q+1] = shi; bi[2*q+1] = cidx; }
            }
        }
    }

    // argmin across the 16 cg-lanes per point (tie -> lowest index)
    #pragma unroll
    for (int i = 0; i < 8; i++) {
        float v = bv[i]; int ix = bi[i];
        #pragma unroll
        for (int off = 1; off <= 8; off <<= 1) {
            float ov = __shfl_xor_sync(0xffffffffu, v, off);
            int   oi = __shfl_xor_sync(0xffffffffu, ix, off);
            if (ov < v || (ov == v && oi < ix)) { v = ov; ix = oi; }
        }
        if (cg == 0) g_assign[b*NN + n0 + 8*pg + i] = ix;
    }
}

// ---------------------------------------------------------------------------
// Stable counting sort of points by cluster (ascending n within cluster).
__global__ void k_sort() {
    __shared__ int hist[CC];
    __shared__ int cursor[CC];
    __shared__ int wt[CC];
    extern __shared__ int W[];   // [32 warps][CC]

    int b = blockIdx.x, tid = threadIdx.x;
    int w = tid >> 5, lane = tid & 31;

    for (int i = tid; i < CC; i += 1024) hist[i] = 0;
    __syncthreads();
    for (int n = tid; n < NN; n += 1024)
        atomicAdd(&hist[g_assign[b*NN + n]], 1);
    __syncthreads();
    if (tid == 0) {
        int run = 0;
        for (int c = 0; c < CC; c++) {
            cursor[c] = run;
            g_off[b*CC + c] = run;
            int h = hist[c];
            g_cnt[b*CC + c] = h;
            run += h;
        }
    }
    __syncthreads();

    for (int wave = 0; wave < NN/1024; wave++) {
        for (int i = tid; i < 32*CC; i += 1024) W[i] = 0;
        __syncthreads();
        int n = wave*1024 + tid;
        int a = g_assign[b*NN + n];
        unsigned mask = __match_any_sync(0xffffffffu, a);
        int rank = __popc(mask & ((1u << lane) - 1u));
        if (rank == 0) W[w*CC + a] = __popc(mask);
        __syncthreads();
        if (tid < CC) {
            int s = 0;
            for (int ww = 0; ww < 32; ww++) {
                int t = W[ww*CC + tid];
                W[ww*CC + tid] = s;
                s += t;
            }
            wt[tid] = s;
        }
        __syncthreads();
        int pos = cursor[a] + W[w*CC + a] + rank;
        g_list[b*NN + pos] = n;
        __syncthreads();
        if (tid < CC) cursor[tid] += wt[tid];
        __syncthreads();
    }
}

// ---------------------------------------------------------------------------
// New centers: sequential ascending-n fp32 adds per (b,c,d), then rn divide.
// Unrolled x8: loads batched (independent), adds strictly in ascending order.
__global__ void k_update(const float* __restrict__ data) {
    __shared__ int listS[128];
    int c = blockIdx.x, b = blockIdx.y, d = threadIdx.x;
    int off = g_off[b*CC + c];
    int cnt = g_cnt[b*CC + c];
    const float* db = data + (size_t)b*NN*DD + d;
    float acc = 0.f;
    for (int base = 0; base < cnt; base += 128) {
        __syncthreads();
        int m = min(128, cnt - base);
        if (d < m) listS[d] = g_list[b*NN + off + base + d];
        __syncthreads();
        int j = 0;
        for (; j + 8 <= m; j += 8) {
            float v0 = __ldg(db + (size_t)listS[j+0]*DD);
            float v1 = __ldg(db + (size_t)listS[j+1]*DD);
            float v2 = __ldg(db + (size_t)listS[j+2]*DD);
            float v3 = __ldg(db + (size_t)listS[j+3]*DD);
            float v4 = __ldg(db + (size_t)listS[j+4]*DD);
            float v5 = __ldg(db + (size_t)listS[j+5]*DD);
            float v6 = __ldg(db + (size_t)listS[j+6]*DD);
            float v7 = __ldg(db + (size_t)listS[j+7]*DD);
            acc = __fadd_rn(acc, v0); acc = __fadd_rn(acc, v1);
            acc = __fadd_rn(acc, v2); acc = __fadd_rn(acc, v3);
            acc = __fadd_rn(acc, v4); acc = __fadd_rn(acc, v5);
            acc = __fadd_rn(acc, v6); acc = __fadd_rn(acc, v7);
        }
        for (; j < m; j++)
            acc = __fadd_rn(acc, __ldg(db + (size_t)listS[j]*DD));
    }
    if (cnt > 0)
        g_centers[(size_t)(b*CC + c)*DD + d] = __fdiv_rn(acc, __int2float_rn(cnt));
}

// d_out = [centers (B*C*D) | (float)assign broadcast over D (B*N*D)]
__global__ void k_output(float* __restrict__ out) {
    size_t i = (size_t)blockIdx.x * blockDim.x + threadIdx.x;
    const size_t nc = (size_t)BB*CC*DD;
    const size_t total = nc + (size_t)BB*NN*DD;
    if (i >= total) return;
    if (i < nc) out[i] = g_centers[i];
    else {
        size_t j = i - nc;
        out[i] = (float)g_assign[j >> 7];
    }
}

// ---------------------------------------------------------------------------
extern "C" void kernel_launch(void* const* d_in, const int* in_sizes, int n_in,
                              void* d_out, int out_size) {
    const float* data      = (const float*)d_in[0];
    const float* centersIn = (const float*)d_in[1];
    float* out = (float*)d_out;

    cudaFuncSetAttribute(k_assign, cudaFuncAttributeMaxDynamicSharedMemorySize,
                         SMEM_BYTES);
    cudaFuncSetAttribute(k_sort, cudaFuncAttributeMaxDynamicSharedMemorySize,
                         32*CC*(int)sizeof(int));

    k_init<<<(BB*CC*DD + 255)/256, 256>>>(centersIn);
    k_t1<<<(BB*NN + 255)/256, 256>>>(data);
    for (int it = 0; it < ITERS; it++) {
        k_prep<<<(BB*CC + 63)/64, 64>>>();
        k_transpose<<<(BB*CC*DD + 255)/256, 256>>>();
        k_assign<<<dim3(NN/TILE_P, BB), 256, SMEM_BYTES>>>(data);
        k_sort<<<BB, 1024, 32*CC*(int)sizeof(int)>>>();
        k_update<<<dim3(CC, BB), 128>>>(data);
    }
    const size_t total = (size_t)BB*CC*DD + (size_t)BB*NN*DD;
    k_output<<<(unsigned)((total + 255)/256), 256>>>(out);
}

// round 13
// speedup vs baseline: 16.2021x; 1.0943x over previous
#include <cuda_runtime.h>
#include <cstdint>

#define BB 8
#define NN 65536
#define CC 512
#define DD 128
#define ITERS 10
#define TILE_P 128
#define QSTRIDE 516            // words per point-quad row (bank-staggered)
#define CROW 64                // words per k-row of non-dup 64-center chunk
#define SEG 64                 // sort segments per batch
#define SEGN (NN/SEG)          // 1024 points per segment

// smem: points 32*516, ONE 32KB center buffer, cnorm 512 (~98.5KB -> 2 CTA/SM)
#define SMEM_BYTES ((32*QSTRIDE + 128*CROW + CC) * 4)

__device__ float g_centers[BB*CC*DD];
__device__ float g_cT[BB*8*DD*64];      // [b][chunk64][k][c&63] k-major centers
__device__ float g_cnorm[BB*CC];
__device__ float g_t1[BB*NN];
__device__ int   g_assign[BB*NN];
__device__ int   g_list[BB*NN];
__device__ int   g_off[BB*CC];
__device__ int   g_cnt[BB*CC];
__device__ int   g_hist[BB*SEG*CC];
__device__ int   g_segoff[BB*SEG*CC];

__device__ __forceinline__ void fma2(unsigned long long &d,
                                     unsigned long long a,
                                     unsigned long long b) {
    asm("fma.rn.f32x2 %0, %1, %2, %0;" : "+l"(d) : "l"(a), "l"(b));
}
__device__ __forceinline__ unsigned long long dup2(float x) {
    unsigned long long r;
    asm("mov.b64 %0, {%1, %1};" : "=l"(r) : "f"(x));
    return r;
}

// ---------------- exact-arithmetic building blocks (DO NOT REORDER) --------
// LLVM-style vectorized sum of v[k]^2: VF=4, IC=2, fma, lanewise, faddp.
__device__ __forceinline__ float norm128_llvm(const float* __restrict__ v) {
    float A0=0.f,A1=0.f,A2=0.f,A3=0.f;
    float B0=0.f,B1=0.f,B2=0.f,B3=0.f;
    #pragma unroll
    for (int i = 0; i < 16; i++) {
        const float* p = v + 8*i;
        A0 = __fmaf_rn(p[0], p[0], A0);
        A1 = __fmaf_rn(p[1], p[1], A1);
        A2 = __fmaf_rn(p[2], p[2], A2);
        A3 = __fmaf_rn(p[3], p[3], A3);
        B0 = __fmaf_rn(p[4], p[4], B0);
        B1 = __fmaf_rn(p[5], p[5], B1);
        B2 = __fmaf_rn(p[6], p[6], B2);
        B3 = __fmaf_rn(p[7], p[7], B3);
    }
    float S0 = __fadd_rn(A0, B0);
    float S1 = __fadd_rn(A1, B1);
    float S2 = __fadd_rn(A2, B2);
    float S3 = __fadd_rn(A3, B3);
    return __fadd_rn(__fadd_rn(S0, S1), __fadd_rn(S2, S3));
}

// ---------------------------------------------------------------------------
__global__ void k_init(const float* __restrict__ centersIn) {
    int i = blockIdx.x * blockDim.x + threadIdx.x;
    if (i < BB*CC*DD) g_centers[i] = centersIn[i];
}
__global__ void k_t1(const float* __restrict__ data) {
    int i = blockIdx.x * blockDim.x + threadIdx.x;
    if (i >= BB*NN) return;
    g_t1[i] = norm128_llvm(data + (size_t)i * DD);
}
__global__ void k_prep() {
    int i = blockIdx.x * blockDim.x + threadIdx.x;
    if (i >= BB*CC) return;
    g_cnorm[i] = norm128_llvm(g_centers + (size_t)i * DD);
}

// k-major chunked transpose: g_cT[b][c>>6][k][c&63] = g_centers[b][c][k]
__global__ void k_transpose() {
    int i = blockIdx.x * blockDim.x + threadIdx.x;
    if (i >= BB*CC*DD) return;
    int k = i & 127;
    int c = (i >> 7) & 511;
    int b = i >> 16;
    float v = g_centers[i];
    g_cT[(((size_t)(b*8 + (c >> 6))*DD + k) << 6) + (c & 63)] = v;
}

// ---------------------------------------------------------------------------
// Assign: exact fp32 fma2 chains, all 512 centers; next chunk prefetched into
// registers during compute. grid=(N/128,B), block=256, 2 CTA/SM,
// per thread: 8 points x 4 centers.
__global__ void __launch_bounds__(256, 2) k_assign(const float* __restrict__ data) {
    extern __shared__ float sm[];
    float* ptsS = sm;                       // [32 quads][QSTRIDE]
    float* cenB = ptsS + 32*QSTRIDE;        // [128 k][CROW]
    float* cnS  = cenB + 128*CROW;          // [512]

    const int b  = blockIdx.y;
    const int n0 = blockIdx.x * TILE_P;
    const int tid = threadIdx.x;
    const int pg = tid >> 4;   // 0..15: points 8pg..8pg+7 (quads 2pg,2pg+1)
    const int cg = tid & 15;   // 0..15: centers 4cg..4cg+3 within chunk

    for (int i = tid; i < CC; i += 256) cnS[i] = g_cnorm[b*CC + i];

    // point tile, quad-packed: ptsS[p>>2][4k + (p&3)] = x_p[k]
    const float* dptr = data + ((size_t)b*NN + n0) * DD;
    for (int idx = tid; idx < TILE_P*32; idx += 256) {
        int p = idx >> 5;
        int q = idx & 31;
        float4 v = __ldg((const float4*)(dptr + (size_t)p*DD) + q);
        float* dst = ptsS + (p >> 2)*QSTRIDE + (p & 3);
        int k4 = q * 4;
        dst[(k4+0)*4] = v.x; dst[(k4+1)*4] = v.y;
        dst[(k4+2)*4] = v.z; dst[(k4+3)*4] = v.w;
    }

    float t1r[8];
    #pragma unroll
    for (int i = 0; i < 8; i++) t1r[i] = g_t1[b*NN + n0 + 8*pg + i];

    float bv[8]; int bi[8];
    #pragma unroll
    for (int i = 0; i < 8; i++) { bv[i] = 3.4e38f; bi[i] = 0; }

    const float4* csrc4 = (const float4*)(g_cT + (size_t)b*8*DD*64);

    // prefetch chunk 0 into registers (32KB = 2048 float4, 8 per thread)
    float4 pre[8];
    #pragma unroll
    for (int j = 0; j < 8; j++)
        pre[j] = __ldg(csrc4 + j*256 + tid);

    const float* q0p = ptsS + (2*pg)*QSTRIDE;
    const float* q1p = q0p + QSTRIDE;
    const float* cw = cenB + 4*cg;

    for (int ch = 0; ch < 8; ch++) {
        __syncthreads();   // prior chunk's compute done before overwrite
        #pragma unroll
        for (int j = 0; j < 8; j++)
            *(float4*)(cenB + (j*256 + tid)*4) = pre[j];
        __syncthreads();   // chunk visible to all warps

        if (ch < 7) {      // prefetch next chunk; latency hidden by compute
            const float4* src = csrc4 + (size_t)(ch + 1)*2048;
            #pragma unroll
            for (int j = 0; j < 8; j++)
                pre[j] = __ldg(src + j*256 + tid);
        }

        unsigned long long acc[4][4];   // [point pair][center j]
        #pragma unroll
        for (int q = 0; q < 4; q++)
            #pragma unroll
            for (int j = 0; j < 4; j++) acc[q][j] = 0ull;

        #pragma unroll 4
        for (int k = 0; k < DD; k++) {
            ulonglong2 Q0 = *(const ulonglong2*)(q0p + 4*k);  // pts 8pg..+3
            ulonglong2 Q1 = *(const ulonglong2*)(q1p + 4*k);  // pts 8pg+4..+7
            float4 C4 = *(const float4*)(cw + k*CROW);
            unsigned long long c0d = dup2(C4.x), c1d = dup2(C4.y);
            unsigned long long c2d = dup2(C4.z), c3d = dup2(C4.w);
            fma2(acc[0][0], Q0.x, c0d); fma2(acc[1][0], Q0.y, c0d);
            fma2(acc[2][0], Q1.x, c0d); fma2(acc[3][0], Q1.y, c0d);
            fma2(acc[0][1], Q0.x, c1d); fma2(acc[1][1], Q0.y, c1d);
            fma2(acc[2][1], Q1.x, c1d); fma2(acc[3][1], Q1.y, c1d);
            fma2(acc[0][2], Q0.x, c2d); fma2(acc[1][2], Q0.y, c2d);
            fma2(acc[2][2], Q1.x, c2d); fma2(acc[3][2], Q1.y, c2d);
            fma2(acc[0][3], Q0.x, c3d); fma2(acc[1][3], Q0.y, c3d);
            fma2(acc[2][3], Q1.x, c3d); fma2(acc[3][3], Q1.y, c3d);
        }

        // epilogue: s = (t1 - 2*dot) + cn, rn ops in reference association
        int c0 = ch * 64 + 4*cg;
        #pragma unroll
        for (int j = 0; j < 4; j++) {
            int cidx = c0 + j;
            float cn = cnS[cidx];
            #pragma unroll
            for (int q = 0; q < 4; q++) {
                float2 f = *(float2*)&acc[q][j];
                float slo = __fadd_rn(__fsub_rn(t1r[2*q],
                                      __fmul_rn(2.0f, f.x)), cn);
                float shi = __fadd_rn(__fsub_rn(t1r[2*q+1],
                                      __fmul_rn(2.0f, f.y)), cn);
                if (slo < bv[2*q])   { bv[2*q]   = slo; bi[2*q]   = cidx; }
                if (shi < bv[2*q+1]) { bv[2*q+1] = shi; bi[2*q+1] = cidx; }
            }
        }
    }

    // argmin across the 16 cg-lanes per point (tie -> lowest index)
    #pragma unroll
    for (int i = 0; i < 8; i++) {
        float v = bv[i]; int ix = bi[i];
        #pragma unroll
        for (int off = 1; off <= 8; off <<= 1) {
            float ov = __shfl_xor_sync(0xffffffffu, v, off);
            int   oi = __shfl_xor_sync(0xffffffffu, ix, off);
            if (ov < v || (ov == v && oi < ix)) { v = ov; ix = oi; }
        }
        if (cg == 0) g_assign[b*NN + n0 + 8*pg + i] = ix;
    }
}

// ---------------------------------------------------------------------------
// Parallel stable counting sort, 3 phases. Order identical to a single
// ascending-n scan: segment asc, warp asc, lane asc.
// Phase A: per-segment histogram. grid (SEG, BB), block 1024.
__global__ void k_hist() {
    __shared__ int h[CC];
    int b = blockIdx.y, seg = blockIdx.x, tid = threadIdx.x;
    int lane = tid & 31;
    if (tid < CC) h[tid] = 0;
    __syncthreads();
    int a = g_assign[b*NN + seg*SEGN + tid];
    unsigned mask = __match_any_sync(0xffffffffu, a);
    int rank = __popc(mask & ((1u << lane) - 1u));
    if (rank == 0) atomicAdd(&h[a], __popc(mask));
    __syncthreads();
    if (tid < CC) g_hist[(b*SEG + seg)*CC + tid] = h[tid];
}

// Phase B: per-(b,c) prefix over segments + per-batch offsets. grid BB, 512.
__global__ void k_scan() {
    __shared__ int tot[CC];
    int b = blockIdx.x, c = threadIdx.x;
    int run = 0;
    for (int s = 0; s < SEG; s++) {
        int t = g_hist[(b*SEG + s)*CC + c];
        g_segoff[(b*SEG + s)*CC + c] = run;
        run += t;
    }
    tot[c] = run;
    g_cnt[b*CC + c] = run;
    __syncthreads();
    if (c == 0) {
        int r2 = 0;
        for (int i = 0; i < CC; i++) {
            g_off[b*CC + i] = r2;
            r2 += tot[i];
        }
    }
}

// Phase C: stable scatter. grid (SEG, BB), block 1024, 64KB dyn smem.
__global__ void k_scatter() {
    extern __shared__ int W[];   // [32 warps][CC]
    int b = blockIdx.y, seg = blockIdx.x, tid = threadIdx.x;
    int w = tid >> 5, lane = tid & 31;
    for (int i = tid; i < 32*CC; i += 1024) W[i] = 0;
    __syncthreads();
    int n = seg*SEGN + tid;
    int a = g_assign[b*NN + n];
    unsigned mask = __match_any_sync(0xffffffffu, a);
    int rank = __popc(mask & ((1u << lane) - 1u));
    if (rank == 0) W[w*CC + a] = __popc(mask);
    __syncthreads();
    if (tid < CC) {
        int s = 0;
        for (int ww = 0; ww < 32; ww++) {
            int t = W[ww*CC + tid];
            W[ww*CC + tid] = s;
            s += t;
        }
    }
    __syncthreads();
    int pos = g_off[b*CC + a] + g_segoff[(b*SEG + seg)*CC + a]
            + W[w*CC + a] + rank;
    g_list[b*NN + pos] = n;
}

// ---------------------------------------------------------------------------
// New centers: sequential ascending-n fp32 adds per (b,c,d), then rn divide.
// Unrolled x8: loads batched (independent), adds strictly in ascending order.
__global__ void k_update(const float* __restrict__ data) {
    __shared__ int listS[128];
    int c = blockIdx.x, b = blockIdx.y, d = threadIdx.x;
    int off = g_off[b*CC + c];
    int cnt = g_cnt[b*CC + c];
    const float* db = data + (size_t)b*NN*DD + d;
    float acc = 0.f;
    for (int base = 0; base < cnt; base += 128) {
        __syncthreads();
        int m = min(128, cnt - base);
        if (d < m) listS[d] = g_list[b*NN + off + base + d];
        __syncthreads();
        int j = 0;
        for (; j + 8 <= m; j += 8) {
            float v0 = __ldg(db + (size_t)listS[j+0]*DD);
            float v1 = __ldg(db + (size_t)listS[j+1]*DD);
            float v2 = __ldg(db + (size_t)listS[j+2]*DD);
            float v3 = __ldg(db + (size_t)listS[j+3]*DD);
            float v4 = __ldg(db + (size_t)listS[j+4]*DD);
            float v5 = __ldg(db + (size_t)listS[j+5]*DD);
            float v6 = __ldg(db + (size_t)listS[j+6]*DD);
            float v7 = __ldg(db + (size_t)listS[j+7]*DD);
            acc = __fadd_rn(acc, v0); acc = __fadd_rn(acc, v1);
            acc = __fadd_rn(acc, v2); acc = __fadd_rn(acc, v3);
            acc = __fadd_rn(acc, v4); acc = __fadd_rn(acc, v5);
            acc = __fadd_rn(acc, v6); acc = __fadd_rn(acc, v7);
        }
        for (; j < m; j++)
            acc = __fadd_rn(acc, __ldg(db + (size_t)listS[j]*DD));
    }
    if (cnt > 0)
        g_centers[(size_t)(b*CC + c)*DD + d] = __fdiv_rn(acc, __int2float_rn(cnt));
}

// d_out = [centers (B*C*D) | (float)assign broadcast over D (B*N*D)]
__global__ void k_output(float* __restrict__ out) {
    size_t i = (size_t)blockIdx.x * blockDim.x + threadIdx.x;
    const size_t nc = (size_t)BB*CC*DD;
    const size_t total = nc + (size_t)BB*NN*DD;
    if (i >= total) return;
    if (i < nc) out[i] = g_centers[i];
    else {
        size_t j = i - nc;
        out[i] = (float)g_assign[j >> 7];
    }
}

// ---------------------------------------------------------------------------
extern "C" void kernel_launch(void* const* d_in, const int* in_sizes, int n_in,
                              void* d_out, int out_size) {
    const float* data      = (const float*)d_in[0];
    const float* centersIn = (const float*)d_in[1];
    float* out = (float*)d_out;

    cudaFuncSetAttribute(k_assign, cudaFuncAttributeMaxDynamicSharedMemorySize,
                         SMEM_BYTES);
    cudaFuncSetAttribute(k_scatter, cudaFuncAttributeMaxDynamicSharedMemorySize,
                         32*CC*(int)sizeof(int));

    k_init<<<(BB*CC*DD + 255)/256, 256>>>(centersIn);
    k_t1<<<(BB*NN + 255)/256, 256>>>(data);
    for (int it = 0; it < ITERS; it++) {
        k_prep<<<(BB*CC + 63)/64, 64>>>();
        k_transpose<<<(BB*CC*DD + 255)/256, 256>>>();
        k_assign<<<dim3(NN/TILE_P, BB), 256, SMEM_BYTES>>>(data);
        k_hist<<<dim3(SEG, BB), 1024>>>();
        k_scan<<<BB, 512>>>();
        k_scatter<<<dim3(SEG, BB), 1024, 32*CC*(int)sizeof(int)>>>();
        k_update<<<dim3(CC, BB), 128>>>(data);
    }
    const size_t total = (size_t)BB*CC*DD + (size_t)BB*NN*DD;
    k_output<<<(unsigned)((total + 255)/256), 256>>>(out);
}